// round 4
// baseline (speedup 1.0000x reference)
#include <cuda_runtime.h>
#include <math.h>

// Problem constants
#define Bc 8
#define Tc 512
#define Dc 768
#define Hc 8
#define HDc 96
#define BTc (Bc*Tc)

// ---------------- scratch (device globals; no cudaMalloc allowed) ----------------
__device__ __align__(16) float g_mean[Bc*Dc];
__device__ int   g_idx_s[Bc];
__device__ int   g_idx_t[Bc];
__device__ __align__(16) float g_xns [BTc*Dc];
__device__ __align__(16) float g_xt  [BTc*Dc];
__device__ __align__(16) float g_qkv [BTc*3*Dc];
__device__ __align__(16) float g_qt  [BTc*Dc];
__device__ __align__(16) float g_kt  [BTc*Dc];
__device__ __align__(16) float g_vt  [BTc*Dc];
__device__ __align__(16) float g_att [BTc*Dc];
__device__ __align__(16) float g_spat[BTc*Dc];
__device__ __align__(16) float g_temp[BTc*Dc];
__device__ __align__(16) float g_cq  [BTc*Dc];
__device__ __align__(16) float g_ckv [BTc*2*Dc];
__device__ __align__(16) float g_x1  [BTc*Dc];
__device__ __align__(16) float g_xm  [BTc*Dc];
__device__ __align__(16) float g_y   [BTc*4*Dc];

__device__ __forceinline__ float gelu_exact(float v) {
    return 0.5f * v * (1.0f + erff(v * 0.70710678118654752f));
}

// ---------------- router part 1: mean over T ----------------
__global__ void rmean_kernel(const float* __restrict__ x, float* __restrict__ mean) {
    int b = blockIdx.x;
    int d = threadIdx.x;            // 768 threads
    float s = 0.f;
    const float* xb = x + (long)b * Tc * Dc + d;
    #pragma unroll 8
    for (int t = 0; t < Tc; t++) s += xb[(long)t * Dc];
    mean[b * Dc + d] = s * (1.0f / (float)Tc);
}

// ---------------- router part 2: MLP -> argmax experts ----------------
__global__ void router_kernel(const float* __restrict__ mean,
                              const float* __restrict__ w1, const float* __restrict__ b1,
                              const float* __restrict__ w2, const float* __restrict__ b2,
                              int* __restrict__ idx_s, int* __restrict__ idx_t) {
    int b = blockIdx.x;
    int j = threadIdx.x;            // 128 threads
    __shared__ float h[128];
    __shared__ float lg[8];
    float a = b1[j];
    const float* mb = mean + b * Dc;
    const float* wr = w1 + j * Dc;
    for (int d = 0; d < Dc; d++) a += mb[d] * wr[d];
    h[j] = gelu_exact(a);
    __syncthreads();
    if (j < 8) {
        float a2 = b2[j];
        const float* wrr = w2 + j * 128;
        for (int i = 0; i < 128; i++) a2 += h[i] * wrr[i];
        lg[j] = a2;
    }
    __syncthreads();
    if (j == 0) {
        int bi = 0;
        for (int i = 1; i < 4; i++) if (lg[i] > lg[bi]) bi = i;
        idx_s[b] = bi;
        int bt = 4;
        for (int i = 5; i < 8; i++) if (lg[i] > lg[bt]) bt = i;
        idx_t[b] = bt - 4;
    }
}

// ---------------- LayerNorm over D=768, one row per block ----------------
__global__ __launch_bounds__(256)
void ln_kernel(const float* __restrict__ x, const float* __restrict__ g,
               const float* __restrict__ bet, float* __restrict__ o) {
    long row = blockIdx.x;
    int tid = threadIdx.x;
    const float* xr = x + row * Dc;
    float v0 = xr[tid], v1 = xr[tid + 256], v2 = xr[tid + 512];
    float s  = v0 + v1 + v2;
    float ss = v0 * v0 + v1 * v1 + v2 * v2;
    #pragma unroll
    for (int off = 16; off > 0; off >>= 1) {
        s  += __shfl_xor_sync(0xffffffffu, s,  off);
        ss += __shfl_xor_sync(0xffffffffu, ss, off);
    }
    __shared__ float rs[8], rss[8];
    int lane = tid & 31, wid = tid >> 5;
    if (lane == 0) { rs[wid] = s; rss[wid] = ss; }
    __syncthreads();
    if (tid == 0) {
        float S = 0.f, SS = 0.f;
        for (int i = 0; i < 8; i++) { S += rs[i]; SS += rss[i]; }
        float mean = S * (1.0f / (float)Dc);
        float var  = SS * (1.0f / (float)Dc) - mean * mean;
        rs[0] = mean;
        rss[0] = rsqrtf(var + 1e-5f);
    }
    __syncthreads();
    float mean = rs[0], inv = rss[0];
    float* orow = o + row * Dc;
    orow[tid]       = (v0 - mean) * inv * g[tid]       + bet[tid];
    orow[tid + 256] = (v1 - mean) * inv * g[tid + 256] + bet[tid + 256];
    orow[tid + 512] = (v2 - mean) * inv * g[tid + 512] + bet[tid + 512];
}

// ---------------- generic GEMM: C = act(A @ W^T + bias) [+ resid] --------------
// Tiles: 128x128x16, 256 threads, 8x8 microtile. All dims are exact multiples.
// W is [N, Kdim] row-major (per expert if eidx != null).
__global__ __launch_bounds__(256, 2)
void gemm128(const float* __restrict__ A, int lda,
             const float* __restrict__ W, int ldw, long wstride,
             const float* __restrict__ bias, int bstride,
             const int* __restrict__ eidx,
             const float* __restrict__ resid,
             float* __restrict__ C, int ldc,
             int Kdim, int act) {
    __shared__ __align__(16) float As[16][132];
    __shared__ __align__(16) float Ws[16][132];

    const int tid = threadIdx.x;
    const int tx = tid & 15;
    const int ty = tid >> 4;
    const int bz = blockIdx.z;
    const long rowBase = ((long)bz * gridDim.x + blockIdx.x) * 128;
    const int n0 = blockIdx.y * 128;

    const int e = eidx ? eidx[bz] : 0;
    const float* Ab = A + rowBase * lda;
    const float* Wb = W + (long)e * wstride + (long)n0 * ldw;
    const float* bb = bias + (long)e * bstride + n0;

    float acc[8][8];
    #pragma unroll
    for (int i = 0; i < 8; i++)
        #pragma unroll
        for (int j = 0; j < 8; j++) acc[i][j] = 0.f;

    const int r0 = tid >> 2;           // 0..63
    const int kq = (tid & 3) * 4;      // 0,4,8,12

    for (int k0 = 0; k0 < Kdim; k0 += 16) {
        #pragma unroll
        for (int half = 0; half < 2; half++) {
            int r = r0 + half * 64;
            float4 va = *(const float4*)(Ab + (long)r * lda + k0 + kq);
            As[kq + 0][r] = va.x; As[kq + 1][r] = va.y;
            As[kq + 2][r] = va.z; As[kq + 3][r] = va.w;
            float4 vw = *(const float4*)(Wb + (long)r * ldw + k0 + kq);
            Ws[kq + 0][r] = vw.x; Ws[kq + 1][r] = vw.y;
            Ws[kq + 2][r] = vw.z; Ws[kq + 3][r] = vw.w;
        }
        __syncthreads();
        #pragma unroll
        for (int k = 0; k < 16; k++) {
            float a[8], w[8];
            *(float4*)(&a[0]) = *(const float4*)(&As[k][ty * 8]);
            *(float4*)(&a[4]) = *(const float4*)(&As[k][ty * 8 + 4]);
            *(float4*)(&w[0]) = *(const float4*)(&Ws[k][tx * 8]);
            *(float4*)(&w[4]) = *(const float4*)(&Ws[k][tx * 8 + 4]);
            #pragma unroll
            for (int i = 0; i < 8; i++)
                #pragma unroll
                for (int j = 0; j < 8; j++)
                    acc[i][j] += a[i] * w[j];
        }
        __syncthreads();
    }

    #pragma unroll
    for (int i = 0; i < 8; i++) {
        long row = rowBase + ty * 8 + i;
        float* Crow = C + row * ldc + n0 + tx * 8;
        const float* Rrow = resid ? (resid + row * ldc + n0 + tx * 8) : (const float*)0;
        float outv[8];
        #pragma unroll
        for (int j = 0; j < 8; j++) {
            float v = acc[i][j] + bb[tx * 8 + j];
            if (act == 1) v = gelu_exact(v);
            if (Rrow) v += Rrow[j];
            outv[j] = v;
        }
        *(float4*)(Crow)     = make_float4(outv[0], outv[1], outv[2], outv[3]);
        *(float4*)(Crow + 4) = make_float4(outv[4], outv[5], outv[6], outv[7]);
    }
}

// ---------------- flash attention: 64 Q-rows per block, HD=96 ----------------
// grid = (T/64, H, B), 256 threads. Online softmax, optional causal mask.
#define ATT_SMEM ((3*64*97 + 64*65) * 4)
__global__ __launch_bounds__(256)
void attn_kernel(const float* __restrict__ Qp, int ldq,
                 const float* __restrict__ Kp, int ldk,
                 const float* __restrict__ Vp, int ldv,
                 float* __restrict__ Op, int ldo, int causal) {
    extern __shared__ float sm[];
    float* Qs = sm;                  // 64 x 97
    float* Ks = sm + 64 * 97;        // 64 x 97
    float* Vs = sm + 2 * 64 * 97;    // 64 x 97
    float* Ps = sm + 3 * 64 * 97;    // 64 x 65

    const int tid = threadIdx.x;
    const int tx = tid & 15;
    const int ty = tid >> 4;
    const int qt = blockIdx.x;
    const int h  = blockIdx.y;
    const int b  = blockIdx.z;
    const float scale = 0.1020620726159658f;   // 1/sqrt(96)

    const float* Qb = Qp + ((long)b * Tc + qt * 64) * ldq + h * HDc;
    const float* Kb = Kp + (long)b * Tc * ldk + h * HDc;
    const float* Vb = Vp + (long)b * Tc * ldv + h * HDc;

    for (int i = tid; i < 64 * 96; i += 256) {
        int r = i / 96, d = i - r * 96;
        Qs[r * 97 + d] = Qb[(long)r * ldq + d];
    }

    float m[4], l[4], o[4][6];
    #pragma unroll
    for (int i = 0; i < 4; i++) {
        m[i] = -1e30f; l[i] = 0.f;
        #pragma unroll
        for (int j = 0; j < 6; j++) o[i][j] = 0.f;
    }

    const int ktmax = causal ? qt : (Tc / 64 - 1);
    for (int kt = 0; kt <= ktmax; kt++) {
        for (int i = tid; i < 64 * 96; i += 256) {
            int r = i / 96, d = i - r * 96;
            Ks[r * 97 + d] = Kb[((long)(kt * 64 + r)) * ldk + d];
            Vs[r * 97 + d] = Vb[((long)(kt * 64 + r)) * ldv + d];
        }
        __syncthreads();

        float s[4][4];
        #pragma unroll
        for (int i = 0; i < 4; i++)
            #pragma unroll
            for (int j = 0; j < 4; j++) s[i][j] = 0.f;

        #pragma unroll 4
        for (int k = 0; k < 96; k++) {
            float a0 = Qs[(ty * 4 + 0) * 97 + k];
            float a1 = Qs[(ty * 4 + 1) * 97 + k];
            float a2 = Qs[(ty * 4 + 2) * 97 + k];
            float a3 = Qs[(ty * 4 + 3) * 97 + k];
            float k0 = Ks[(tx * 4 + 0) * 97 + k];
            float k1 = Ks[(tx * 4 + 1) * 97 + k];
            float k2 = Ks[(tx * 4 + 2) * 97 + k];
            float k3 = Ks[(tx * 4 + 3) * 97 + k];
            s[0][0] += a0 * k0; s[0][1] += a0 * k1; s[0][2] += a0 * k2; s[0][3] += a0 * k3;
            s[1][0] += a1 * k0; s[1][1] += a1 * k1; s[1][2] += a1 * k2; s[1][3] += a1 * k3;
            s[2][0] += a2 * k0; s[2][1] += a2 * k1; s[2][2] += a2 * k2; s[2][3] += a2 * k3;
            s[3][0] += a3 * k0; s[3][1] += a3 * k1; s[3][2] += a3 * k2; s[3][3] += a3 * k3;
        }

        const int q0 = qt * 64 + ty * 4;
        const int c0 = kt * 64 + tx * 4;
        #pragma unroll
        for (int i = 0; i < 4; i++)
            #pragma unroll
            for (int j = 0; j < 4; j++) {
                float v = s[i][j] * scale;
                if (causal && (c0 + j > q0 + i)) v = -1e30f;
                s[i][j] = v;
            }

        #pragma unroll
        for (int i = 0; i < 4; i++) {
            float mt = fmaxf(fmaxf(s[i][0], s[i][1]), fmaxf(s[i][2], s[i][3]));
            #pragma unroll
            for (int off = 8; off > 0; off >>= 1)
                mt = fmaxf(mt, __shfl_xor_sync(0xffffffffu, mt, off));
            float mn = fmaxf(m[i], mt);
            float alpha = __expf(m[i] - mn);
            float ps = 0.f;
            #pragma unroll
            for (int j = 0; j < 4; j++) {
                float p = __expf(s[i][j] - mn);
                s[i][j] = p;
                ps += p;
            }
            #pragma unroll
            for (int off = 8; off > 0; off >>= 1)
                ps += __shfl_xor_sync(0xffffffffu, ps, off);
            l[i] = l[i] * alpha + ps;
            m[i] = mn;
            #pragma unroll
            for (int j = 0; j < 6; j++) o[i][j] *= alpha;
            #pragma unroll
            for (int j = 0; j < 4; j++)
                Ps[(ty * 4 + i) * 65 + tx * 4 + j] = s[i][j];
        }
        __syncthreads();

        #pragma unroll 4
        for (int c = 0; c < 64; c++) {
            float p0 = Ps[(ty * 4 + 0) * 65 + c];
            float p1 = Ps[(ty * 4 + 1) * 65 + c];
            float p2 = Ps[(ty * 4 + 2) * 65 + c];
            float p3 = Ps[(ty * 4 + 3) * 65 + c];
            #pragma unroll
            for (int j = 0; j < 6; j++) {
                float vv = Vs[c * 97 + tx * 6 + j];
                o[0][j] += p0 * vv;
                o[1][j] += p1 * vv;
                o[2][j] += p2 * vv;
                o[3][j] += p3 * vv;
            }
        }
        __syncthreads();
    }

    float* Ob = Op + ((long)b * Tc + qt * 64) * ldo + h * HDc;
    #pragma unroll
    for (int i = 0; i < 4; i++) {
        float inv = 1.0f / l[i];
        #pragma unroll
        for (int j = 0; j < 6; j++)
            Ob[(long)(ty * 4 + i) * ldo + tx * 6 + j] = o[i][j] * inv;
    }
}

// ---------------- host driver ----------------
extern "C" void kernel_launch(void* const* d_in, const int* in_sizes, int n_in,
                              void* d_out, int out_size) {
    (void)in_sizes; (void)n_in; (void)out_size;
    const float* x       = (const float*)d_in[0];
    const float* r_w1    = (const float*)d_in[1];
    const float* r_b1    = (const float*)d_in[2];
    const float* r_w2    = (const float*)d_in[3];
    const float* r_b2    = (const float*)d_in[4];
    const float* ns_g    = (const float*)d_in[5];
    const float* ns_b    = (const float*)d_in[6];
    const float* nt_g    = (const float*)d_in[7];
    const float* nt_b    = (const float*)d_in[8];
    const float* nm_g    = (const float*)d_in[9];
    const float* nm_b    = (const float*)d_in[10];
    const float* sp_wqkv = (const float*)d_in[11];
    const float* sp_bqkv = (const float*)d_in[12];
    const float* sp_wo   = (const float*)d_in[13];
    const float* sp_bo   = (const float*)d_in[14];
    const float* tp_wq   = (const float*)d_in[15];
    const float* tp_bq   = (const float*)d_in[16];
    const float* tp_wk   = (const float*)d_in[17];
    const float* tp_bk   = (const float*)d_in[18];
    const float* tp_wv   = (const float*)d_in[19];
    const float* tp_bv   = (const float*)d_in[20];
    const float* tp_wo   = (const float*)d_in[21];
    const float* tp_bo   = (const float*)d_in[22];
    const float* c_wqkv  = (const float*)d_in[23];
    const float* c_bqkv  = (const float*)d_in[24];
    const float* c_wo    = (const float*)d_in[25];
    const float* c_bo    = (const float*)d_in[26];
    const float* m_w1    = (const float*)d_in[27];
    const float* m_b1    = (const float*)d_in[28];
    const float* m_w2    = (const float*)d_in[29];
    const float* m_b2    = (const float*)d_in[30];
    float* out = (float*)d_out;

    float *mean, *xns, *xt, *qkv, *qt, *kt, *vt, *att, *spat, *temp, *cq, *ckv, *x1, *xm, *y;
    int *idx_s, *idx_t;
    cudaGetSymbolAddress((void**)&mean,  g_mean);
    cudaGetSymbolAddress((void**)&idx_s, g_idx_s);
    cudaGetSymbolAddress((void**)&idx_t, g_idx_t);
    cudaGetSymbolAddress((void**)&xns,   g_xns);
    cudaGetSymbolAddress((void**)&xt,    g_xt);
    cudaGetSymbolAddress((void**)&qkv,   g_qkv);
    cudaGetSymbolAddress((void**)&qt,    g_qt);
    cudaGetSymbolAddress((void**)&kt,    g_kt);
    cudaGetSymbolAddress((void**)&vt,    g_vt);
    cudaGetSymbolAddress((void**)&att,   g_att);
    cudaGetSymbolAddress((void**)&spat,  g_spat);
    cudaGetSymbolAddress((void**)&temp,  g_temp);
    cudaGetSymbolAddress((void**)&cq,    g_cq);
    cudaGetSymbolAddress((void**)&ckv,   g_ckv);
    cudaGetSymbolAddress((void**)&x1,    g_x1);
    cudaGetSymbolAddress((void**)&xm,    g_xm);
    cudaGetSymbolAddress((void**)&y,     g_y);

    cudaFuncSetAttribute(attn_kernel, cudaFuncAttributeMaxDynamicSharedMemorySize, ATT_SMEM);

    // router
    rmean_kernel<<<Bc, Dc>>>(x, mean);
    router_kernel<<<Bc, 128>>>(mean, r_w1, r_b1, r_w2, r_b2, idx_s, idx_t);

    // layernorms for both branches
    ln_kernel<<<BTc, 256>>>(x, ns_g, ns_b, xns);
    ln_kernel<<<BTc, 256>>>(x, nt_g, nt_b, xt);

    // ---- spatial branch ----
    gemm128<<<dim3(4, 18, 8), 256>>>(xns, Dc, sp_wqkv, Dc, (long)3 * Dc * Dc,
                                     sp_bqkv, 3 * Dc, idx_s, (const float*)0,
                                     qkv, 3 * Dc, Dc, 0);
    attn_kernel<<<dim3(8, 8, 8), 256, ATT_SMEM>>>(qkv, 3 * Dc, qkv + Dc, 3 * Dc,
                                                  qkv + 2 * Dc, 3 * Dc, att, Dc, 0);
    gemm128<<<dim3(4, 6, 8), 256>>>(att, Dc, sp_wo, Dc, (long)Dc * Dc,
                                    sp_bo, Dc, idx_s, (const float*)0,
                                    spat, Dc, Dc, 0);

    // ---- temporal branch (causal, residual with normed input) ----
    gemm128<<<dim3(4, 6, 8), 256>>>(xt, Dc, tp_wq, Dc, (long)Dc * Dc,
                                    tp_bq, Dc, idx_t, (const float*)0, qt, Dc, Dc, 0);
    gemm128<<<dim3(4, 6, 8), 256>>>(xt, Dc, tp_wk, Dc, (long)Dc * Dc,
                                    tp_bk, Dc, idx_t, (const float*)0, kt, Dc, Dc, 0);
    gemm128<<<dim3(4, 6, 8), 256>>>(xt, Dc, tp_wv, Dc, (long)Dc * Dc,
                                    tp_bv, Dc, idx_t, (const float*)0, vt, Dc, Dc, 0);
    attn_kernel<<<dim3(8, 8, 8), 256, ATT_SMEM>>>(qt, Dc, kt, Dc, vt, Dc, att, Dc, 1);
    gemm128<<<dim3(4, 6, 8), 256>>>(att, Dc, tp_wo, Dc, (long)Dc * Dc,
                                    tp_bo, Dc, idx_t, xt, temp, Dc, Dc, 0);

    // ---- cross attention fusing the two branches ----
    gemm128<<<dim3(32, 6, 1), 256>>>(spat, Dc, c_wqkv, Dc, 0L,
                                     c_bqkv, 0, (const int*)0, (const float*)0,
                                     cq, Dc, Dc, 0);
    gemm128<<<dim3(32, 12, 1), 256>>>(temp, Dc, c_wqkv + Dc * Dc, Dc, 0L,
                                      c_bqkv + Dc, 0, (const int*)0, (const float*)0,
                                      ckv, 2 * Dc, Dc, 0);
    attn_kernel<<<dim3(8, 8, 8), 256, ATT_SMEM>>>(cq, Dc, ckv, 2 * Dc,
                                                  ckv + Dc, 2 * Dc, att, Dc, 0);
    gemm128<<<dim3(32, 6, 1), 256>>>(att, Dc, c_wo, Dc, 0L,
                                     c_bo, 0, (const int*)0, x,
                                     x1, Dc, Dc, 0);

    // ---- MLP with residual ----
    ln_kernel<<<BTc, 256>>>(x1, nm_g, nm_b, xm);
    gemm128<<<dim3(32, 24, 1), 256>>>(xm, Dc, m_w1, Dc, 0L,
                                      m_b1, 0, (const int*)0, (const float*)0,
                                      y, 4 * Dc, Dc, 1);
    gemm128<<<dim3(32, 6, 1), 256>>>(y, 4 * Dc, m_w2, 4 * Dc, 0L,
                                     m_b2, 0, (const int*)0, x1,
                                     out, Dc, 4 * Dc, 0);
}

// round 5
// speedup vs baseline: 1.7843x; 1.7843x over previous
#include <cuda_runtime.h>
#include <math.h>
#include <stdint.h>

// Problem constants
#define Bc 8
#define Tc 512
#define Dc 768
#define Hc 8
#define HDc 96
#define BTc (Bc*Tc)

// ---------------- scratch (device globals; no cudaMalloc allowed) ----------------
__device__ __align__(16) float g_mean[Bc*Dc];
__device__ int   g_idx_s[Bc];
__device__ int   g_idx_t[Bc];
__device__ __align__(16) float g_xns [BTc*Dc];
__device__ __align__(16) float g_xt  [BTc*Dc];
__device__ __align__(16) float g_qkv [BTc*3*Dc];
__device__ __align__(16) float g_qt  [BTc*Dc];
__device__ __align__(16) float g_kt  [BTc*Dc];
__device__ __align__(16) float g_vt  [BTc*Dc];
__device__ __align__(16) float g_att [BTc*Dc];
__device__ __align__(16) float g_spat[BTc*Dc];
__device__ __align__(16) float g_temp[BTc*Dc];
__device__ __align__(16) float g_cq  [BTc*Dc];
__device__ __align__(16) float g_ckv [BTc*2*Dc];
__device__ __align__(16) float g_x1  [BTc*Dc];
__device__ __align__(16) float g_xm  [BTc*Dc];
__device__ __align__(16) float g_y   [BTc*4*Dc];

__device__ __forceinline__ float gelu_exact(float v) {
    return 0.5f * v * (1.0f + erff(v * 0.70710678118654752f));
}

__device__ __forceinline__ uint32_t f2tf32(float f) {
    uint32_t u;
    asm volatile("cvt.rna.tf32.f32 %0, %1;" : "=r"(u) : "f"(f));
    return u;
}

__device__ __forceinline__ void mma_tf32(float* c, const uint32_t* a, const uint32_t* b) {
    asm volatile(
        "mma.sync.aligned.m16n8k8.row.col.f32.tf32.tf32.f32 "
        "{%0,%1,%2,%3}, {%4,%5,%6,%7}, {%8,%9}, {%0,%1,%2,%3};\n"
        : "+f"(c[0]), "+f"(c[1]), "+f"(c[2]), "+f"(c[3])
        : "r"(a[0]), "r"(a[1]), "r"(a[2]), "r"(a[3]),
          "r"(b[0]), "r"(b[1]));
}

// ---------------- router part 1: mean over T ----------------
__global__ void rmean_kernel(const float* __restrict__ x, float* __restrict__ mean) {
    int b = blockIdx.x;
    int d = threadIdx.x;            // 768 threads
    float s = 0.f;
    const float* xb = x + (long)b * Tc * Dc + d;
    #pragma unroll 8
    for (int t = 0; t < Tc; t++) s += xb[(long)t * Dc];
    mean[b * Dc + d] = s * (1.0f / (float)Tc);
}

// ---------------- router part 2: MLP -> argmax experts ----------------
__global__ void router_kernel(const float* __restrict__ mean,
                              const float* __restrict__ w1, const float* __restrict__ b1,
                              const float* __restrict__ w2, const float* __restrict__ b2,
                              int* __restrict__ idx_s, int* __restrict__ idx_t) {
    int b = blockIdx.x;
    int j = threadIdx.x;            // 128 threads
    __shared__ float h[128];
    __shared__ float lg[8];
    float a = b1[j];
    const float* mb = mean + b * Dc;
    const float* wr = w1 + j * Dc;
    for (int d = 0; d < Dc; d++) a += mb[d] * wr[d];
    h[j] = gelu_exact(a);
    __syncthreads();
    if (j < 8) {
        float a2 = b2[j];
        const float* wrr = w2 + j * 128;
        for (int i = 0; i < 128; i++) a2 += h[i] * wrr[i];
        lg[j] = a2;
    }
    __syncthreads();
    if (j == 0) {
        int bi = 0;
        for (int i = 1; i < 4; i++) if (lg[i] > lg[bi]) bi = i;
        idx_s[b] = bi;
        int bt = 4;
        for (int i = 5; i < 8; i++) if (lg[i] > lg[bt]) bt = i;
        idx_t[b] = bt - 4;
    }
}

// ---------------- LayerNorm over D=768, one row per block ----------------
__global__ __launch_bounds__(256)
void ln_kernel(const float* __restrict__ x, const float* __restrict__ g,
               const float* __restrict__ bet, float* __restrict__ o) {
    long row = blockIdx.x;
    int tid = threadIdx.x;
    const float* xr = x + row * Dc;
    float v0 = xr[tid], v1 = xr[tid + 256], v2 = xr[tid + 512];
    float s  = v0 + v1 + v2;
    float ss = v0 * v0 + v1 * v1 + v2 * v2;
    #pragma unroll
    for (int off = 16; off > 0; off >>= 1) {
        s  += __shfl_xor_sync(0xffffffffu, s,  off);
        ss += __shfl_xor_sync(0xffffffffu, ss, off);
    }
    __shared__ float rs[8], rss[8];
    int lane = tid & 31, wid = tid >> 5;
    if (lane == 0) { rs[wid] = s; rss[wid] = ss; }
    __syncthreads();
    if (tid == 0) {
        float S = 0.f, SS = 0.f;
        for (int i = 0; i < 8; i++) { S += rs[i]; SS += rss[i]; }
        float mean = S * (1.0f / (float)Dc);
        float var  = SS * (1.0f / (float)Dc) - mean * mean;
        rs[0] = mean;
        rss[0] = rsqrtf(var + 1e-5f);
    }
    __syncthreads();
    float mean = rs[0], inv = rss[0];
    float* orow = o + row * Dc;
    orow[tid]       = (v0 - mean) * inv * g[tid]       + bet[tid];
    orow[tid + 256] = (v1 - mean) * inv * g[tid + 256] + bet[tid + 256];
    orow[tid + 512] = (v2 - mean) * inv * g[tid + 512] + bet[tid + 512];
}

// ------------- tensor-core GEMM: C = act(A @ W^T + bias) [+ resid] ------------
// TF32 mma.sync m16n8k8, fp32 accumulate. Tiles 128x128x32. 256 threads = 8 warps
// arranged 2(M)x4(N), warp tile 64x32. W is [N, Kdim] row-major (per expert if
// eidx != null). All dims are exact multiples of the tile sizes.
__global__ __launch_bounds__(256)
void gemm_tc(const float* __restrict__ A, int lda,
             const float* __restrict__ W, int ldw, long wstride,
             const float* __restrict__ bias, int bstride,
             const int* __restrict__ eidx,
             const float* __restrict__ resid,
             float* __restrict__ C, int ldc,
             int Kdim, int act) {
    __shared__ uint32_t As[128][36];   // [m][k], pad 36 -> conflict-free frags
    __shared__ uint32_t Bs[128][36];   // [n][k]

    const int tid  = threadIdx.x;
    const int wid  = tid >> 5;
    const int lane = tid & 31;
    const int grp  = lane >> 2;        // 0..7
    const int tg   = lane & 3;         // 0..3
    const int warpM = wid & 1;         // 0..1  (64 rows each)
    const int warpN = wid >> 1;        // 0..3  (32 cols each)

    const int bz = blockIdx.z;
    const long rowBase = ((long)bz * gridDim.x + blockIdx.x) * 128;
    const int n0 = blockIdx.y * 128;

    const int e = eidx ? eidx[bz] : 0;
    const float* Ab = A + rowBase * lda;
    const float* Wb = W + (long)e * wstride + (long)n0 * ldw;
    const float* bb = bias + (long)e * bstride + n0;

    float acc[4][4][4];
    #pragma unroll
    for (int i = 0; i < 4; i++)
        #pragma unroll
        for (int j = 0; j < 4; j++)
            #pragma unroll
            for (int r = 0; r < 4; r++) acc[i][j][r] = 0.f;

    // gmem tile load mapping: 128 rows x 32 k floats; 2 threads/row, 16 floats each
    const int lrow = tid >> 1;
    const int lcol = (tid & 1) * 16;
    const float* aptr = Ab + (long)lrow * lda + lcol;
    const float* wptr = Wb + (long)lrow * ldw + lcol;

    float4 fa[4], fw[4];
    #pragma unroll
    for (int q = 0; q < 4; q++) {
        fa[q] = *(const float4*)(aptr + q * 4);
        fw[q] = *(const float4*)(wptr + q * 4);
    }
    #pragma unroll
    for (int q = 0; q < 4; q++) {
        uint4 ua = make_uint4(f2tf32(fa[q].x), f2tf32(fa[q].y), f2tf32(fa[q].z), f2tf32(fa[q].w));
        uint4 uw = make_uint4(f2tf32(fw[q].x), f2tf32(fw[q].y), f2tf32(fw[q].z), f2tf32(fw[q].w));
        *(uint4*)&As[lrow][lcol + q * 4] = ua;
        *(uint4*)&Bs[lrow][lcol + q * 4] = uw;
    }
    __syncthreads();

    const int nK = Kdim >> 5;
    for (int kt = 0; kt < nK; kt++) {
        const bool more = (kt + 1 < nK);
        if (more) {
            const float* ap = aptr + (kt + 1) * 32;
            const float* wp = wptr + (kt + 1) * 32;
            #pragma unroll
            for (int q = 0; q < 4; q++) {
                fa[q] = *(const float4*)(ap + q * 4);
                fw[q] = *(const float4*)(wp + q * 4);
            }
        }

        #pragma unroll
        for (int kk = 0; kk < 4; kk++) {
            const int k = kk * 8 + tg;
            uint32_t afr[4][4];
            #pragma unroll
            for (int i = 0; i < 4; i++) {
                const int m = warpM * 64 + i * 16 + grp;
                afr[i][0] = As[m][k];
                afr[i][1] = As[m + 8][k];
                afr[i][2] = As[m][k + 4];
                afr[i][3] = As[m + 8][k + 4];
            }
            uint32_t bfr[4][2];
            #pragma unroll
            for (int j = 0; j < 4; j++) {
                const int n = warpN * 32 + j * 8 + grp;
                bfr[j][0] = Bs[n][k];
                bfr[j][1] = Bs[n][k + 4];
            }
            #pragma unroll
            for (int i = 0; i < 4; i++)
                #pragma unroll
                for (int j = 0; j < 4; j++)
                    mma_tf32(acc[i][j], afr[i], bfr[j]);
        }

        if (more) {
            __syncthreads();
            #pragma unroll
            for (int q = 0; q < 4; q++) {
                uint4 ua = make_uint4(f2tf32(fa[q].x), f2tf32(fa[q].y), f2tf32(fa[q].z), f2tf32(fa[q].w));
                uint4 uw = make_uint4(f2tf32(fw[q].x), f2tf32(fw[q].y), f2tf32(fw[q].z), f2tf32(fw[q].w));
                *(uint4*)&As[lrow][lcol + q * 4] = ua;
                *(uint4*)&Bs[lrow][lcol + q * 4] = uw;
            }
            __syncthreads();
        }
    }

    // epilogue: c regs -> rows {m0, m0+8}, cols {c0, c0+1}
    #pragma unroll
    for (int i = 0; i < 4; i++) {
        const long m0 = rowBase + warpM * 64 + i * 16 + grp;
        #pragma unroll
        for (int j = 0; j < 4; j++) {
            const int coff = warpN * 32 + j * 8 + 2 * tg;
            const int col = n0 + coff;
            #pragma unroll
            for (int rr = 0; rr < 2; rr++) {
                const long row = m0 + rr * 8;
                float v0 = acc[i][j][rr * 2 + 0] + bb[coff];
                float v1 = acc[i][j][rr * 2 + 1] + bb[coff + 1];
                if (act == 1) { v0 = gelu_exact(v0); v1 = gelu_exact(v1); }
                if (resid) {
                    const float* rp = resid + row * ldc + col;
                    v0 += rp[0]; v1 += rp[1];
                }
                *(float2*)(C + row * ldc + col) = make_float2(v0, v1);
            }
        }
    }
}

// ---------------- flash attention: 64 Q-rows per block, HD=96 ----------------
// grid = (T/64, H, B), 256 threads. Online softmax, optional causal mask.
#define ATT_SMEM ((3*64*97 + 64*65) * 4)
__global__ __launch_bounds__(256)
void attn_kernel(const float* __restrict__ Qp, int ldq,
                 const float* __restrict__ Kp, int ldk,
                 const float* __restrict__ Vp, int ldv,
                 float* __restrict__ Op, int ldo, int causal) {
    extern __shared__ float sm[];
    float* Qs = sm;                  // 64 x 97
    float* Ks = sm + 64 * 97;        // 64 x 97
    float* Vs = sm + 2 * 64 * 97;    // 64 x 97
    float* Ps = sm + 3 * 64 * 97;    // 64 x 65

    const int tid = threadIdx.x;
    const int tx = tid & 15;
    const int ty = tid >> 4;
    const int qt = blockIdx.x;
    const int h  = blockIdx.y;
    const int b  = blockIdx.z;
    const float scale = 0.1020620726159658f;   // 1/sqrt(96)

    const float* Qb = Qp + ((long)b * Tc + qt * 64) * ldq + h * HDc;
    const float* Kb = Kp + (long)b * Tc * ldk + h * HDc;
    const float* Vb = Vp + (long)b * Tc * ldv + h * HDc;

    for (int i = tid; i < 64 * 96; i += 256) {
        int r = i / 96, d = i - r * 96;
        Qs[r * 97 + d] = Qb[(long)r * ldq + d];
    }

    float m[4], l[4], o[4][6];
    #pragma unroll
    for (int i = 0; i < 4; i++) {
        m[i] = -1e30f; l[i] = 0.f;
        #pragma unroll
        for (int j = 0; j < 6; j++) o[i][j] = 0.f;
    }

    const int ktmax = causal ? qt : (Tc / 64 - 1);
    for (int kt = 0; kt <= ktmax; kt++) {
        for (int i = tid; i < 64 * 96; i += 256) {
            int r = i / 96, d = i - r * 96;
            Ks[r * 97 + d] = Kb[((long)(kt * 64 + r)) * ldk + d];
            Vs[r * 97 + d] = Vb[((long)(kt * 64 + r)) * ldv + d];
        }
        __syncthreads();

        float s[4][4];
        #pragma unroll
        for (int i = 0; i < 4; i++)
            #pragma unroll
            for (int j = 0; j < 4; j++) s[i][j] = 0.f;

        #pragma unroll 4
        for (int k = 0; k < 96; k++) {
            float a0 = Qs[(ty * 4 + 0) * 97 + k];
            float a1 = Qs[(ty * 4 + 1) * 97 + k];
            float a2 = Qs[(ty * 4 + 2) * 97 + k];
            float a3 = Qs[(ty * 4 + 3) * 97 + k];
            float k0 = Ks[(tx * 4 + 0) * 97 + k];
            float k1 = Ks[(tx * 4 + 1) * 97 + k];
            float k2 = Ks[(tx * 4 + 2) * 97 + k];
            float k3 = Ks[(tx * 4 + 3) * 97 + k];
            s[0][0] += a0 * k0; s[0][1] += a0 * k1; s[0][2] += a0 * k2; s[0][3] += a0 * k3;
            s[1][0] += a1 * k0; s[1][1] += a1 * k1; s[1][2] += a1 * k2; s[1][3] += a1 * k3;
            s[2][0] += a2 * k0; s[2][1] += a2 * k1; s[2][2] += a2 * k2; s[2][3] += a2 * k3;
            s[3][0] += a3 * k0; s[3][1] += a3 * k1; s[3][2] += a3 * k2; s[3][3] += a3 * k3;
        }

        const int q0 = qt * 64 + ty * 4;
        const int c0 = kt * 64 + tx * 4;
        #pragma unroll
        for (int i = 0; i < 4; i++)
            #pragma unroll
            for (int j = 0; j < 4; j++) {
                float v = s[i][j] * scale;
                if (causal && (c0 + j > q0 + i)) v = -1e30f;
                s[i][j] = v;
            }

        #pragma unroll
        for (int i = 0; i < 4; i++) {
            float mt = fmaxf(fmaxf(s[i][0], s[i][1]), fmaxf(s[i][2], s[i][3]));
            #pragma unroll
            for (int off = 8; off > 0; off >>= 1)
                mt = fmaxf(mt, __shfl_xor_sync(0xffffffffu, mt, off));
            float mn = fmaxf(m[i], mt);
            float alpha = __expf(m[i] - mn);
            float ps = 0.f;
            #pragma unroll
            for (int j = 0; j < 4; j++) {
                float p = __expf(s[i][j] - mn);
                s[i][j] = p;
                ps += p;
            }
            #pragma unroll
            for (int off = 8; off > 0; off >>= 1)
                ps += __shfl_xor_sync(0xffffffffu, ps, off);
            l[i] = l[i] * alpha + ps;
            m[i] = mn;
            #pragma unroll
            for (int j = 0; j < 6; j++) o[i][j] *= alpha;
            #pragma unroll
            for (int j = 0; j < 4; j++)
                Ps[(ty * 4 + i) * 65 + tx * 4 + j] = s[i][j];
        }
        __syncthreads();

        #pragma unroll 4
        for (int c = 0; c < 64; c++) {
            float p0 = Ps[(ty * 4 + 0) * 65 + c];
            float p1 = Ps[(ty * 4 + 1) * 65 + c];
            float p2 = Ps[(ty * 4 + 2) * 65 + c];
            float p3 = Ps[(ty * 4 + 3) * 65 + c];
            #pragma unroll
            for (int j = 0; j < 6; j++) {
                float vv = Vs[c * 97 + tx * 6 + j];
                o[0][j] += p0 * vv;
                o[1][j] += p1 * vv;
                o[2][j] += p2 * vv;
                o[3][j] += p3 * vv;
            }
        }
        __syncthreads();
    }

    float* Ob = Op + ((long)b * Tc + qt * 64) * ldo + h * HDc;
    #pragma unroll
    for (int i = 0; i < 4; i++) {
        float inv = 1.0f / l[i];
        #pragma unroll
        for (int j = 0; j < 6; j++)
            Ob[(long)(ty * 4 + i) * ldo + tx * 6 + j] = o[i][j] * inv;
    }
}

// ---------------- host driver ----------------
extern "C" void kernel_launch(void* const* d_in, const int* in_sizes, int n_in,
                              void* d_out, int out_size) {
    (void)in_sizes; (void)n_in; (void)out_size;
    const float* x       = (const float*)d_in[0];
    const float* r_w1    = (const float*)d_in[1];
    const float* r_b1    = (const float*)d_in[2];
    const float* r_w2    = (const float*)d_in[3];
    const float* r_b2    = (const float*)d_in[4];
    const float* ns_g    = (const float*)d_in[5];
    const float* ns_b    = (const float*)d_in[6];
    const float* nt_g    = (const float*)d_in[7];
    const float* nt_b    = (const float*)d_in[8];
    const float* nm_g    = (const float*)d_in[9];
    const float* nm_b    = (const float*)d_in[10];
    const float* sp_wqkv = (const float*)d_in[11];
    const float* sp_bqkv = (const float*)d_in[12];
    const float* sp_wo   = (const float*)d_in[13];
    const float* sp_bo   = (const float*)d_in[14];
    const float* tp_wq   = (const float*)d_in[15];
    const float* tp_bq   = (const float*)d_in[16];
    const float* tp_wk   = (const float*)d_in[17];
    const float* tp_bk   = (const float*)d_in[18];
    const float* tp_wv   = (const float*)d_in[19];
    const float* tp_bv   = (const float*)d_in[20];
    const float* tp_wo   = (const float*)d_in[21];
    const float* tp_bo   = (const float*)d_in[22];
    const float* c_wqkv  = (const float*)d_in[23];
    const float* c_bqkv  = (const float*)d_in[24];
    const float* c_wo    = (const float*)d_in[25];
    const float* c_bo    = (const float*)d_in[26];
    const float* m_w1    = (const float*)d_in[27];
    const float* m_b1    = (const float*)d_in[28];
    const float* m_w2    = (const float*)d_in[29];
    const float* m_b2    = (const float*)d_in[30];
    float* out = (float*)d_out;

    float *mean, *xns, *xt, *qkv, *qt, *kt, *vt, *att, *spat, *temp, *cq, *ckv, *x1, *xm, *y;
    int *idx_s, *idx_t;
    cudaGetSymbolAddress((void**)&mean,  g_mean);
    cudaGetSymbolAddress((void**)&idx_s, g_idx_s);
    cudaGetSymbolAddress((void**)&idx_t, g_idx_t);
    cudaGetSymbolAddress((void**)&xns,   g_xns);
    cudaGetSymbolAddress((void**)&xt,    g_xt);
    cudaGetSymbolAddress((void**)&qkv,   g_qkv);
    cudaGetSymbolAddress((void**)&qt,    g_qt);
    cudaGetSymbolAddress((void**)&kt,    g_kt);
    cudaGetSymbolAddress((void**)&vt,    g_vt);
    cudaGetSymbolAddress((void**)&att,   g_att);
    cudaGetSymbolAddress((void**)&spat,  g_spat);
    cudaGetSymbolAddress((void**)&temp,  g_temp);
    cudaGetSymbolAddress((void**)&cq,    g_cq);
    cudaGetSymbolAddress((void**)&ckv,   g_ckv);
    cudaGetSymbolAddress((void**)&x1,    g_x1);
    cudaGetSymbolAddress((void**)&xm,    g_xm);
    cudaGetSymbolAddress((void**)&y,     g_y);

    cudaFuncSetAttribute(attn_kernel, cudaFuncAttributeMaxDynamicSharedMemorySize, ATT_SMEM);

    // router
    rmean_kernel<<<Bc, Dc>>>(x, mean);
    router_kernel<<<Bc, 128>>>(mean, r_w1, r_b1, r_w2, r_b2, idx_s, idx_t);

    // layernorms for both branches
    ln_kernel<<<BTc, 256>>>(x, ns_g, ns_b, xns);
    ln_kernel<<<BTc, 256>>>(x, nt_g, nt_b, xt);

    // ---- spatial branch ----
    gemm_tc<<<dim3(4, 18, 8), 256>>>(xns, Dc, sp_wqkv, Dc, (long)3 * Dc * Dc,
                                     sp_bqkv, 3 * Dc, idx_s, (const float*)0,
                                     qkv, 3 * Dc, Dc, 0);
    attn_kernel<<<dim3(8, 8, 8), 256, ATT_SMEM>>>(qkv, 3 * Dc, qkv + Dc, 3 * Dc,
                                                  qkv + 2 * Dc, 3 * Dc, att, Dc, 0);
    gemm_tc<<<dim3(4, 6, 8), 256>>>(att, Dc, sp_wo, Dc, (long)Dc * Dc,
                                    sp_bo, Dc, idx_s, (const float*)0,
                                    spat, Dc, Dc, 0);

    // ---- temporal branch (causal, residual with normed input) ----
    gemm_tc<<<dim3(4, 6, 8), 256>>>(xt, Dc, tp_wq, Dc, (long)Dc * Dc,
                                    tp_bq, Dc, idx_t, (const float*)0, qt, Dc, Dc, 0);
    gemm_tc<<<dim3(4, 6, 8), 256>>>(xt, Dc, tp_wk, Dc, (long)Dc * Dc,
                                    tp_bk, Dc, idx_t, (const float*)0, kt, Dc, Dc, 0);
    gemm_tc<<<dim3(4, 6, 8), 256>>>(xt, Dc, tp_wv, Dc, (long)Dc * Dc,
                                    tp_bv, Dc, idx_t, (const float*)0, vt, Dc, Dc, 0);
    attn_kernel<<<dim3(8, 8, 8), 256, ATT_SMEM>>>(qt, Dc, kt, Dc, vt, Dc, att, Dc, 1);
    gemm_tc<<<dim3(4, 6, 8), 256>>>(att, Dc, tp_wo, Dc, (long)Dc * Dc,
                                    tp_bo, Dc, idx_t, xt, temp, Dc, Dc, 0);

    // ---- cross attention fusing the two branches ----
    gemm_tc<<<dim3(32, 6, 1), 256>>>(spat, Dc, c_wqkv, Dc, 0L,
                                     c_bqkv, 0, (const int*)0, (const float*)0,
                                     cq, Dc, Dc, 0);
    gemm_tc<<<dim3(32, 12, 1), 256>>>(temp, Dc, c_wqkv + Dc * Dc, Dc, 0L,
                                      c_bqkv + Dc, 0, (const int*)0, (const float*)0,
                                      ckv, 2 * Dc, Dc, 0);
    attn_kernel<<<dim3(8, 8, 8), 256, ATT_SMEM>>>(cq, Dc, ckv, 2 * Dc,
                                                  ckv + Dc, 2 * Dc, att, Dc, 0);
    gemm_tc<<<dim3(32, 6, 1), 256>>>(att, Dc, c_wo, Dc, 0L,
                                     c_bo, 0, (const int*)0, x,
                                     x1, Dc, Dc, 0);

    // ---- MLP with residual ----
    ln_kernel<<<BTc, 256>>>(x1, nm_g, nm_b, xm);
    gemm_tc<<<dim3(32, 24, 1), 256>>>(xm, Dc, m_w1, Dc, 0L,
                                      m_b1, 0, (const int*)0, (const float*)0,
                                      y, 4 * Dc, Dc, 1);
    gemm_tc<<<dim3(32, 6, 1), 256>>>(y, 4 * Dc, m_w2, 4 * Dc, 0L,
                                     m_b2, 0, (const int*)0, x1,
                                     out, Dc, 4 * Dc, 0);
}

// round 8
// speedup vs baseline: 2.3255x; 1.3033x over previous
#include <cuda_runtime.h>
#include <math.h>
#include <stdint.h>

// Problem constants
#define Bc 8
#define Tc 512
#define Dc 768
#define Hc 8
#define HDc 96
#define BTc (Bc*Tc)

// ---------------- scratch (device globals; no cudaMalloc allowed) ----------------
__device__ __align__(16) float g_mean[Bc*Dc];
__device__ int   g_idx_s[Bc];
__device__ int   g_idx_t[Bc];
__device__ __align__(16) float g_xns [BTc*Dc];
__device__ __align__(16) float g_xt  [BTc*Dc];
__device__ __align__(16) float g_qkv [BTc*3*Dc];
__device__ __align__(16) float g_qt  [BTc*Dc];
__device__ __align__(16) float g_kt  [BTc*Dc];
__device__ __align__(16) float g_vt  [BTc*Dc];
__device__ __align__(16) float g_att [BTc*Dc];
__device__ __align__(16) float g_spat[BTc*Dc];
__device__ __align__(16) float g_temp[BTc*Dc];
__device__ __align__(16) float g_cq  [BTc*Dc];
__device__ __align__(16) float g_ckv [BTc*2*Dc];
__device__ __align__(16) float g_x1  [BTc*Dc];
__device__ __align__(16) float g_xm  [BTc*Dc];
__device__ __align__(16) float g_y   [BTc*4*Dc];

__device__ __forceinline__ float gelu_exact(float v) {
    return 0.5f * v * (1.0f + erff(v * 0.70710678118654752f));
}

__device__ __forceinline__ uint32_t f2tf32(float f) {
    uint32_t u;
    asm volatile("cvt.rna.tf32.f32 %0, %1;" : "=r"(u) : "f"(f));
    return u;
}

__device__ __forceinline__ void mma_tf32(float* c, const uint32_t* a, const uint32_t* b) {
    asm volatile(
        "mma.sync.aligned.m16n8k8.row.col.f32.tf32.tf32.f32 "
        "{%0,%1,%2,%3}, {%4,%5,%6,%7}, {%8,%9}, {%0,%1,%2,%3};\n"
        : "+f"(c[0]), "+f"(c[1]), "+f"(c[2]), "+f"(c[3])
        : "r"(a[0]), "r"(a[1]), "r"(a[2]), "r"(a[3]),
          "r"(b[0]), "r"(b[1]));
}

// ---------------- router part 1: mean over T ----------------
__global__ void rmean_kernel(const float* __restrict__ x, float* __restrict__ mean) {
    int b = blockIdx.x;
    int d = threadIdx.x;            // 768 threads
    float s = 0.f;
    const float* xb = x + (long)b * Tc * Dc + d;
    #pragma unroll 8
    for (int t = 0; t < Tc; t++) s += xb[(long)t * Dc];
    mean[b * Dc + d] = s * (1.0f / (float)Tc);
}

// ---------------- router part 2: MLP -> argmax experts ----------------
__global__ void router_kernel(const float* __restrict__ mean,
                              const float* __restrict__ w1, const float* __restrict__ b1,
                              const float* __restrict__ w2, const float* __restrict__ b2,
                              int* __restrict__ idx_s, int* __restrict__ idx_t) {
    int b = blockIdx.x;
    int j = threadIdx.x;            // 128 threads
    __shared__ float h[128];
    __shared__ float lg[8];
    float a = b1[j];
    const float* mb = mean + b * Dc;
    const float* wr = w1 + j * Dc;
    for (int d = 0; d < Dc; d++) a += mb[d] * wr[d];
    h[j] = gelu_exact(a);
    __syncthreads();
    if (j < 8) {
        float a2 = b2[j];
        const float* wrr = w2 + j * 128;
        for (int i = 0; i < 128; i++) a2 += h[i] * wrr[i];
        lg[j] = a2;
    }
    __syncthreads();
    if (j == 0) {
        int bi = 0;
        for (int i = 1; i < 4; i++) if (lg[i] > lg[bi]) bi = i;
        idx_s[b] = bi;
        int bt = 4;
        for (int i = 5; i < 8; i++) if (lg[i] > lg[bt]) bt = i;
        idx_t[b] = bt - 4;
    }
}

// ---------------- LayerNorm over D=768, one row per block ----------------
__global__ __launch_bounds__(256)
void ln_kernel(const float* __restrict__ x, const float* __restrict__ g,
               const float* __restrict__ bet, float* __restrict__ o) {
    long row = blockIdx.x;
    int tid = threadIdx.x;
    const float* xr = x + row * Dc;
    float v0 = xr[tid], v1 = xr[tid + 256], v2 = xr[tid + 512];
    float s  = v0 + v1 + v2;
    float ss = v0 * v0 + v1 * v1 + v2 * v2;
    #pragma unroll
    for (int off = 16; off > 0; off >>= 1) {
        s  += __shfl_xor_sync(0xffffffffu, s,  off);
        ss += __shfl_xor_sync(0xffffffffu, ss, off);
    }
    __shared__ float rs[8], rss[8];
    int lane = tid & 31, wid = tid >> 5;
    if (lane == 0) { rs[wid] = s; rss[wid] = ss; }
    __syncthreads();
    if (tid == 0) {
        float S = 0.f, SS = 0.f;
        for (int i = 0; i < 8; i++) { S += rs[i]; SS += rss[i]; }
        float mean = S * (1.0f / (float)Dc);
        float var  = SS * (1.0f / (float)Dc) - mean * mean;
        rs[0] = mean;
        rss[0] = rsqrtf(var + 1e-5f);
    }
    __syncthreads();
    float mean = rs[0], inv = rss[0];
    float* orow = o + row * Dc;
    orow[tid]       = (v0 - mean) * inv * g[tid]       + bet[tid];
    orow[tid + 256] = (v1 - mean) * inv * g[tid + 256] + bet[tid + 256];
    orow[tid + 512] = (v2 - mean) * inv * g[tid + 512] + bet[tid + 512];
}

// ------------- tensor-core GEMM: C = act(A @ W^T + bias) [+ resid] ------------
// TF32 mma.sync m16n8k8, fp32 accumulate. Tiles 128x128x32. 256 threads = 8 warps
// arranged 2(M)x4(N), warp tile 64x32. Double-buffered smem (ping-pong), one
// __syncthreads per k-tile. W is [N, Kdim] row-major (per expert if eidx != null).
#define GEMM_SMEM (2 * 2 * 128 * 36 * 4)
__global__ __launch_bounds__(256)
void gemm_tc(const float* __restrict__ A, int lda,
             const float* __restrict__ W, int ldw, long wstride,
             const float* __restrict__ bias, int bstride,
             const int* __restrict__ eidx,
             const float* __restrict__ resid,
             float* __restrict__ C, int ldc,
             int Kdim, int act) {
    extern __shared__ uint32_t gsm[];   // [buf][A(128*36) | B(128*36)]

    const int tid  = threadIdx.x;
    const int wid  = tid >> 5;
    const int lane = tid & 31;
    const int grp  = lane >> 2;        // 0..7
    const int tg   = lane & 3;         // 0..3
    const int warpM = wid & 1;         // 0..1  (64 rows each)
    const int warpN = wid >> 1;        // 0..3  (32 cols each)

    const int bz = blockIdx.z;
    const long rowBase = ((long)bz * gridDim.x + blockIdx.x) * 128;
    const int n0 = blockIdx.y * 128;

    const int e = eidx ? eidx[bz] : 0;
    const float* Ab = A + rowBase * lda;
    const float* Wb = W + (long)e * wstride + (long)n0 * ldw;
    const float* bb = bias + (long)e * bstride + n0;

    float acc[4][4][4];
    #pragma unroll
    for (int i = 0; i < 4; i++)
        #pragma unroll
        for (int j = 0; j < 4; j++)
            #pragma unroll
            for (int r = 0; r < 4; r++) acc[i][j][r] = 0.f;

    // gmem tile load mapping: 128 rows x 32 k floats; 2 threads/row, 16 floats each
    const int lrow = tid >> 1;
    const int lcol = (tid & 1) * 16;
    const float* aptr = Ab + (long)lrow * lda + lcol;
    const float* wptr = Wb + (long)lrow * ldw + lcol;

    float4 fa[4], fw[4];
    #pragma unroll
    for (int q = 0; q < 4; q++) {
        fa[q] = *(const float4*)(aptr + q * 4);
        fw[q] = *(const float4*)(wptr + q * 4);
    }
    {
        uint32_t* As0 = gsm;
        uint32_t* Bs0 = gsm + 128 * 36;
        #pragma unroll
        for (int q = 0; q < 4; q++) {
            uint4 ua = make_uint4(f2tf32(fa[q].x), f2tf32(fa[q].y), f2tf32(fa[q].z), f2tf32(fa[q].w));
            uint4 uw = make_uint4(f2tf32(fw[q].x), f2tf32(fw[q].y), f2tf32(fw[q].z), f2tf32(fw[q].w));
            *(uint4*)&As0[lrow * 36 + lcol + q * 4] = ua;
            *(uint4*)&Bs0[lrow * 36 + lcol + q * 4] = uw;
        }
    }
    __syncthreads();

    const int nK = Kdim >> 5;
    for (int kt = 0; kt < nK; kt++) {
        const int cur = kt & 1;
        const uint32_t* Asb = gsm + cur * (2 * 128 * 36);
        const uint32_t* Bsb = Asb + 128 * 36;
        const bool more = (kt + 1 < nK);
        if (more) {
            const float* ap = aptr + (kt + 1) * 32;
            const float* wp = wptr + (kt + 1) * 32;
            #pragma unroll
            for (int q = 0; q < 4; q++) {
                fa[q] = *(const float4*)(ap + q * 4);
                fw[q] = *(const float4*)(wp + q * 4);
            }
        }

        #pragma unroll
        for (int kk = 0; kk < 4; kk++) {
            const int k = kk * 8 + tg;
            uint32_t afr[4][4];
            #pragma unroll
            for (int i = 0; i < 4; i++) {
                const int m = warpM * 64 + i * 16 + grp;
                afr[i][0] = Asb[m * 36 + k];
                afr[i][1] = Asb[(m + 8) * 36 + k];
                afr[i][2] = Asb[m * 36 + k + 4];
                afr[i][3] = Asb[(m + 8) * 36 + k + 4];
            }
            uint32_t bfr[4][2];
            #pragma unroll
            for (int j = 0; j < 4; j++) {
                const int n = warpN * 32 + j * 8 + grp;
                bfr[j][0] = Bsb[n * 36 + k];
                bfr[j][1] = Bsb[n * 36 + k + 4];
            }
            #pragma unroll
            for (int i = 0; i < 4; i++)
                #pragma unroll
                for (int j = 0; j < 4; j++)
                    mma_tf32(acc[i][j], afr[i], bfr[j]);
        }

        if (more) {
            uint32_t* Asn = gsm + (cur ^ 1) * (2 * 128 * 36);
            uint32_t* Bsn = Asn + 128 * 36;
            #pragma unroll
            for (int q = 0; q < 4; q++) {
                uint4 ua = make_uint4(f2tf32(fa[q].x), f2tf32(fa[q].y), f2tf32(fa[q].z), f2tf32(fa[q].w));
                uint4 uw = make_uint4(f2tf32(fw[q].x), f2tf32(fw[q].y), f2tf32(fw[q].z), f2tf32(fw[q].w));
                *(uint4*)&Asn[lrow * 36 + lcol + q * 4] = ua;
                *(uint4*)&Bsn[lrow * 36 + lcol + q * 4] = uw;
            }
            __syncthreads();
        }
    }

    // epilogue: c regs -> rows {m0, m0+8}, cols {c0, c0+1}
    #pragma unroll
    for (int i = 0; i < 4; i++) {
        const long m0 = rowBase + warpM * 64 + i * 16 + grp;
        #pragma unroll
        for (int j = 0; j < 4; j++) {
            const int coff = warpN * 32 + j * 8 + 2 * tg;
            const int col = n0 + coff;
            #pragma unroll
            for (int rr = 0; rr < 2; rr++) {
                const long row = m0 + rr * 8;
                float v0 = acc[i][j][rr * 2 + 0] + bb[coff];
                float v1 = acc[i][j][rr * 2 + 1] + bb[coff + 1];
                if (act == 1) { v0 = gelu_exact(v0); v1 = gelu_exact(v1); }
                if (resid) {
                    const float* rp = resid + row * ldc + col;
                    v0 += rp[0]; v1 += rp[1];
                }
                *(float2*)(C + row * ldc + col) = make_float2(v0, v1);
            }
        }
    }
}

// ---------- tensor-core flash attention: 64 Q-rows/CTA, 64-col KV tiles ----------
// 128 threads = 4 warps; warp w owns Q rows [16w, 16w+16) -> softmax is warp-local.
// TF32 mma for both S = Q K^T and O += P V. grid = (T/64, H, B).
#define AT_LD  104   // Qs/Ks/Vs row pitch (uint32), 104 % 32 == 8 -> conflict-free frags
#define AT_LDP 72    // Ps row pitch,          72 % 32 == 8 -> conflict-free frags
#define ATT_SMEM ((3*64*AT_LD + 64*AT_LDP) * 4)
__global__ __launch_bounds__(128)
void attn_tc(const float* __restrict__ Qp, int ldq,
             const float* __restrict__ Kp, int ldk,
             const float* __restrict__ Vp, int ldv,
             float* __restrict__ Op, int ldo, int causal) {
    extern __shared__ uint32_t asm_[];
    uint32_t* Qs = asm_;                    // [64][AT_LD]  tf32
    uint32_t* Ks = asm_ + 64 * AT_LD;       // [64][AT_LD]  tf32 (rows = key idx)
    uint32_t* Vs = asm_ + 2 * 64 * AT_LD;   // [64][AT_LD]  tf32 (rows = key idx)
    uint32_t* Ps = asm_ + 3 * 64 * AT_LD;   // [64][AT_LDP] tf32

    const int tid  = threadIdx.x;
    const int lane = tid & 31;
    const int w    = tid >> 5;             // 0..3
    const int grp  = lane >> 2;            // 0..7
    const int tg   = lane & 3;             // 0..3
    const int qt = blockIdx.x;
    const int h  = blockIdx.y;
    const int b  = blockIdx.z;
    const float scale = 0.1020620726159658f;   // 1/sqrt(96)

    const float* Qb = Qp + ((long)b * Tc + qt * 64) * ldq + h * HDc;
    const float* Kb = Kp + (long)b * Tc * ldk + h * HDc;
    const float* Vb = Vp + (long)b * Tc * ldv + h * HDc;

    // load Q tile (64 x 96) as tf32
    for (int i = tid; i < 64 * 24; i += 128) {
        int r = i / 24, c = (i % 24) * 4;
        float4 v = *(const float4*)(Qb + (long)r * ldq + c);
        *(uint4*)&Qs[r * AT_LD + c] =
            make_uint4(f2tf32(v.x), f2tf32(v.y), f2tf32(v.z), f2tf32(v.w));
    }

    float m_lo = -1e30f, m_hi = -1e30f, l_lo = 0.f, l_hi = 0.f;
    float oacc[12][4];
    #pragma unroll
    for (int d = 0; d < 12; d++)
        #pragma unroll
        for (int r = 0; r < 4; r++) oacc[d][r] = 0.f;

    const int m0 = w * 16 + grp;           // local row (lo); hi = m0+8
    const int rowg_lo = qt * 64 + m0;
    const int rowg_hi = rowg_lo + 8;

    const int ktmax = causal ? qt : (Tc / 64 - 1);
    for (int kt = 0; kt <= ktmax; kt++) {
        __syncthreads();                   // Ks/Vs (and first-iter Qs) reuse guard
        for (int i = tid; i < 64 * 24; i += 128) {
            int r = i / 24, c = (i % 24) * 4;
            float4 vk = *(const float4*)(Kb + (long)(kt * 64 + r) * ldk + c);
            float4 vv = *(const float4*)(Vb + (long)(kt * 64 + r) * ldv + c);
            *(uint4*)&Ks[r * AT_LD + c] =
                make_uint4(f2tf32(vk.x), f2tf32(vk.y), f2tf32(vk.z), f2tf32(vk.w));
            *(uint4*)&Vs[r * AT_LD + c] =
                make_uint4(f2tf32(vv.x), f2tf32(vv.y), f2tf32(vv.z), f2tf32(vv.w));
        }
        __syncthreads();

        // ---- S = Q K^T  (warp tile 16 x 64) ----
        float sacc[8][4];
        #pragma unroll
        for (int j = 0; j < 8; j++)
            #pragma unroll
            for (int r = 0; r < 4; r++) sacc[j][r] = 0.f;

        #pragma unroll
        for (int kk = 0; kk < 12; kk++) {
            const int k = kk * 8 + tg;
            uint32_t a[4];
            a[0] = Qs[m0 * AT_LD + k];
            a[1] = Qs[(m0 + 8) * AT_LD + k];
            a[2] = Qs[m0 * AT_LD + k + 4];
            a[3] = Qs[(m0 + 8) * AT_LD + k + 4];
            #pragma unroll
            for (int j = 0; j < 8; j++) {
                uint32_t bf[2];
                const int n = j * 8 + grp;
                bf[0] = Ks[n * AT_LD + k];
                bf[1] = Ks[n * AT_LD + k + 4];
                mma_tf32(sacc[j], a, bf);
            }
        }

        // ---- scale + causal mask + online softmax (warp-local) ----
        const bool dmask = causal && (kt == qt);
        float mt_lo = -1e30f, mt_hi = -1e30f;
        #pragma unroll
        for (int j = 0; j < 8; j++) {
            const int c = kt * 64 + j * 8 + 2 * tg;
            float s0 = sacc[j][0] * scale;
            float s1 = sacc[j][1] * scale;
            float s2 = sacc[j][2] * scale;
            float s3 = sacc[j][3] * scale;
            if (dmask) {
                if (c     > rowg_lo) s0 = -1e30f;
                if (c + 1 > rowg_lo) s1 = -1e30f;
                if (c     > rowg_hi) s2 = -1e30f;
                if (c + 1 > rowg_hi) s3 = -1e30f;
            }
            sacc[j][0] = s0; sacc[j][1] = s1; sacc[j][2] = s2; sacc[j][3] = s3;
            mt_lo = fmaxf(mt_lo, fmaxf(s0, s1));
            mt_hi = fmaxf(mt_hi, fmaxf(s2, s3));
        }
        mt_lo = fmaxf(mt_lo, __shfl_xor_sync(0xffffffffu, mt_lo, 1));
        mt_lo = fmaxf(mt_lo, __shfl_xor_sync(0xffffffffu, mt_lo, 2));
        mt_hi = fmaxf(mt_hi, __shfl_xor_sync(0xffffffffu, mt_hi, 1));
        mt_hi = fmaxf(mt_hi, __shfl_xor_sync(0xffffffffu, mt_hi, 2));

        const float mn_lo = fmaxf(m_lo, mt_lo);
        const float mn_hi = fmaxf(m_hi, mt_hi);
        const float al_lo = __expf(m_lo - mn_lo);
        const float al_hi = __expf(m_hi - mn_hi);

        float ps_lo = 0.f, ps_hi = 0.f;
        #pragma unroll
        for (int j = 0; j < 8; j++) {
            const int c = j * 8 + 2 * tg;
            float p0 = __expf(sacc[j][0] - mn_lo);
            float p1 = __expf(sacc[j][1] - mn_lo);
            float p2 = __expf(sacc[j][2] - mn_hi);
            float p3 = __expf(sacc[j][3] - mn_hi);
            ps_lo += p0 + p1;
            ps_hi += p2 + p3;
            Ps[m0 * AT_LDP + c]           = f2tf32(p0);
            Ps[m0 * AT_LDP + c + 1]       = f2tf32(p1);
            Ps[(m0 + 8) * AT_LDP + c]     = f2tf32(p2);
            Ps[(m0 + 8) * AT_LDP + c + 1] = f2tf32(p3);
        }
        ps_lo += __shfl_xor_sync(0xffffffffu, ps_lo, 1);
        ps_lo += __shfl_xor_sync(0xffffffffu, ps_lo, 2);
        ps_hi += __shfl_xor_sync(0xffffffffu, ps_hi, 1);
        ps_hi += __shfl_xor_sync(0xffffffffu, ps_hi, 2);

        l_lo = l_lo * al_lo + ps_lo;  m_lo = mn_lo;
        l_hi = l_hi * al_hi + ps_hi;  m_hi = mn_hi;
        #pragma unroll
        for (int d = 0; d < 12; d++) {
            oacc[d][0] *= al_lo; oacc[d][1] *= al_lo;
            oacc[d][2] *= al_hi; oacc[d][3] *= al_hi;
        }
        __syncwarp();   // Ps rows owned by this warp: STS -> LDS ordering

        // ---- O += P V  (warp tile 16 x 96) ----
        #pragma unroll
        for (int kc = 0; kc < 8; kc++) {
            const int k = kc * 8 + tg;
            uint32_t a[4];
            a[0] = Ps[m0 * AT_LDP + k];
            a[1] = Ps[(m0 + 8) * AT_LDP + k];
            a[2] = Ps[m0 * AT_LDP + k + 4];
            a[3] = Ps[(m0 + 8) * AT_LDP + k + 4];
            #pragma unroll
            for (int d = 0; d < 12; d++) {
                uint32_t bf[2];
                const int n = d * 8 + grp;
                bf[0] = Vs[k * AT_LD + n];
                bf[1] = Vs[(k + 4) * AT_LD + n];
                mma_tf32(oacc[d], a, bf);
            }
        }
    }

    // ---- epilogue: normalize by l, write O ----
    const float inv_lo = 1.0f / l_lo;
    const float inv_hi = 1.0f / l_hi;
    float* Ob = Op + ((long)b * Tc + qt * 64 + w * 16) * ldo + h * HDc;
    #pragma unroll
    for (int d = 0; d < 12; d++) {
        const int c = d * 8 + 2 * tg;
        *(float2*)(Ob + (long)grp * ldo + c) =
            make_float2(oacc[d][0] * inv_lo, oacc[d][1] * inv_lo);
        *(float2*)(Ob + (long)(grp + 8) * ldo + c) =
            make_float2(oacc[d][2] * inv_hi, oacc[d][3] * inv_hi);
    }
}

// ---------------- host driver ----------------
extern "C" void kernel_launch(void* const* d_in, const int* in_sizes, int n_in,
                              void* d_out, int out_size) {
    (void)in_sizes; (void)n_in; (void)out_size;
    const float* x       = (const float*)d_in[0];
    const float* r_w1    = (const float*)d_in[1];
    const float* r_b1    = (const float*)d_in[2];
    const float* r_w2    = (const float*)d_in[3];
    const float* r_b2    = (const float*)d_in[4];
    const float* ns_g    = (const float*)d_in[5];
    const float* ns_b    = (const float*)d_in[6];
    const float* nt_g    = (const float*)d_in[7];
    const float* nt_b    = (const float*)d_in[8];
    const float* nm_g    = (const float*)d_in[9];
    const float* nm_b    = (const float*)d_in[10];
    const float* sp_wqkv = (const float*)d_in[11];
    const float* sp_bqkv = (const float*)d_in[12];
    const float* sp_wo   = (const float*)d_in[13];
    const float* sp_bo   = (const float*)d_in[14];
    const float* tp_wq   = (const float*)d_in[15];
    const float* tp_bq   = (const float*)d_in[16];
    const float* tp_wk   = (const float*)d_in[17];
    const float* tp_bk   = (const float*)d_in[18];
    const float* tp_wv   = (const float*)d_in[19];
    const float* tp_bv   = (const float*)d_in[20];
    const float* tp_wo   = (const float*)d_in[21];
    const float* tp_bo   = (const float*)d_in[22];
    const float* c_wqkv  = (const float*)d_in[23];
    const float* c_bqkv  = (const float*)d_in[24];
    const float* c_wo    = (const float*)d_in[25];
    const float* c_bo    = (const float*)d_in[26];
    const float* m_w1    = (const float*)d_in[27];
    const float* m_b1    = (const float*)d_in[28];
    const float* m_w2    = (const float*)d_in[29];
    const float* m_b2    = (const float*)d_in[30];
    float* out = (float*)d_out;

    float *mean, *xns, *xt, *qkv, *qt, *kt, *vt, *att, *spat, *temp, *cq, *ckv, *x1, *xm, *y;
    int *idx_s, *idx_t;
    cudaGetSymbolAddress((void**)&mean,  g_mean);
    cudaGetSymbolAddress((void**)&idx_s, g_idx_s);
    cudaGetSymbolAddress((void**)&idx_t, g_idx_t);
    cudaGetSymbolAddress((void**)&xns,   g_xns);
    cudaGetSymbolAddress((void**)&xt,    g_xt);
    cudaGetSymbolAddress((void**)&qkv,   g_qkv);
    cudaGetSymbolAddress((void**)&qt,    g_qt);
    cudaGetSymbolAddress((void**)&kt,    g_kt);
    cudaGetSymbolAddress((void**)&vt,    g_vt);
    cudaGetSymbolAddress((void**)&att,   g_att);
    cudaGetSymbolAddress((void**)&spat,  g_spat);
    cudaGetSymbolAddress((void**)&temp,  g_temp);
    cudaGetSymbolAddress((void**)&cq,    g_cq);
    cudaGetSymbolAddress((void**)&ckv,   g_ckv);
    cudaGetSymbolAddress((void**)&x1,    g_x1);
    cudaGetSymbolAddress((void**)&xm,    g_xm);
    cudaGetSymbolAddress((void**)&y,     g_y);

    cudaFuncSetAttribute(gemm_tc, cudaFuncAttributeMaxDynamicSharedMemorySize, GEMM_SMEM);
    cudaFuncSetAttribute(attn_tc, cudaFuncAttributeMaxDynamicSharedMemorySize, ATT_SMEM);

    // router
    rmean_kernel<<<Bc, Dc>>>(x, mean);
    router_kernel<<<Bc, 128>>>(mean, r_w1, r_b1, r_w2, r_b2, idx_s, idx_t);

    // layernorms for both branches
    ln_kernel<<<BTc, 256>>>(x, ns_g, ns_b, xns);
    ln_kernel<<<BTc, 256>>>(x, nt_g, nt_b, xt);

    // ---- spatial branch ----
    gemm_tc<<<dim3(4, 18, 8), 256, GEMM_SMEM>>>(xns, Dc, sp_wqkv, Dc, (long)3 * Dc * Dc,
                                     sp_bqkv, 3 * Dc, idx_s, (const float*)0,
                                     qkv, 3 * Dc, Dc, 0);
    attn_tc<<<dim3(8, 8, 8), 128, ATT_SMEM>>>(qkv, 3 * Dc, qkv + Dc, 3 * Dc,
                                              qkv + 2 * Dc, 3 * Dc, att, Dc, 0);
    gemm_tc<<<dim3(4, 6, 8), 256, GEMM_SMEM>>>(att, Dc, sp_wo, Dc, (long)Dc * Dc,
                                    sp_bo, Dc, idx_s, (const float*)0,
                                    spat, Dc, Dc, 0);

    // ---- temporal branch (causal, residual with normed input) ----
    gemm_tc<<<dim3(4, 6, 8), 256, GEMM_SMEM>>>(xt, Dc, tp_wq, Dc, (long)Dc * Dc,
                                    tp_bq, Dc, idx_t, (const float*)0, qt, Dc, Dc, 0);
    gemm_tc<<<dim3(4, 6, 8), 256, GEMM_SMEM>>>(xt, Dc, tp_wk, Dc, (long)Dc * Dc,
                                    tp_bk, Dc, idx_t, (const float*)0, kt, Dc, Dc, 0);
    gemm_tc<<<dim3(4, 6, 8), 256, GEMM_SMEM>>>(xt, Dc, tp_wv, Dc, (long)Dc * Dc,
                                    tp_bv, Dc, idx_t, (const float*)0, vt, Dc, Dc, 0);
    attn_tc<<<dim3(8, 8, 8), 128, ATT_SMEM>>>(qt, Dc, kt, Dc, vt, Dc, att, Dc, 1);
    gemm_tc<<<dim3(4, 6, 8), 256, GEMM_SMEM>>>(att, Dc, tp_wo, Dc, (long)Dc * Dc,
                                    tp_bo, Dc, idx_t, xt, temp, Dc, Dc, 0);

    // ---- cross attention fusing the two branches ----
    gemm_tc<<<dim3(32, 6, 1), 256, GEMM_SMEM>>>(spat, Dc, c_wqkv, Dc, 0L,
                                     c_bqkv, 0, (const int*)0, (const float*)0,
                                     cq, Dc, Dc, 0);
    gemm_tc<<<dim3(32, 12, 1), 256, GEMM_SMEM>>>(temp, Dc, c_wqkv + Dc * Dc, Dc, 0L,
                                      c_bqkv + Dc, 0, (const int*)0, (const float*)0,
                                      ckv, 2 * Dc, Dc, 0);
    attn_tc<<<dim3(8, 8, 8), 128, ATT_SMEM>>>(cq, Dc, ckv, 2 * Dc,
                                              ckv + Dc, 2 * Dc, att, Dc, 0);
    gemm_tc<<<dim3(32, 6, 1), 256, GEMM_SMEM>>>(att, Dc, c_wo, Dc, 0L,
                                     c_bo, 0, (const int*)0, x,
                                     x1, Dc, Dc, 0);

    // ---- MLP with residual ----
    ln_kernel<<<BTc, 256>>>(x1, nm_g, nm_b, xm);
    gemm_tc<<<dim3(32, 24, 1), 256, GEMM_SMEM>>>(xm, Dc, m_w1, Dc, 0L,
                                      m_b1, 0, (const int*)0, (const float*)0,
                                      y, 4 * Dc, Dc, 1);
    gemm_tc<<<dim3(32, 6, 1), 256, GEMM_SMEM>>>(y, 4 * Dc, m_w2, 4 * Dc, 0L,
                                     m_b2, 0, (const int*)0, x1,
                                     out, Dc, 4 * Dc, 0);
}

// round 10
// speedup vs baseline: 2.3898x; 1.0276x over previous
#include <cuda_runtime.h>
#include <math.h>
#include <stdint.h>

// Problem constants
#define Bc 8
#define Tc 512
#define Dc 768
#define Hc 8
#define HDc 96
#define BTc (Bc*Tc)

// ---------------- scratch (device globals; no cudaMalloc allowed) ----------------
__device__ __align__(16) float g_mean[Bc*Dc];
__device__ int   g_idx_s[Bc];
__device__ int   g_idx_t[Bc];
__device__ __align__(16) float g_xns [BTc*Dc];
__device__ __align__(16) float g_xt  [BTc*Dc];
__device__ __align__(16) float g_qkv [BTc*3*Dc];
__device__ __align__(16) float g_qt  [BTc*Dc];
__device__ __align__(16) float g_kt  [BTc*Dc];
__device__ __align__(16) float g_vt  [BTc*Dc];
__device__ __align__(16) float g_att [BTc*Dc];
__device__ __align__(16) float g_spat[BTc*Dc];
__device__ __align__(16) float g_temp[BTc*Dc];
__device__ __align__(16) float g_cq  [BTc*Dc];
__device__ __align__(16) float g_ckv [BTc*2*Dc];
__device__ __align__(16) float g_x1  [BTc*Dc];
__device__ __align__(16) float g_xm  [BTc*Dc];
__device__ __align__(16) float g_y   [BTc*4*Dc];

__device__ __forceinline__ float gelu_exact(float v) {
    return 0.5f * v * (1.0f + erff(v * 0.70710678118654752f));
}

__device__ __forceinline__ void mma_tf32(float* c, const uint32_t* a, const uint32_t* b) {
    asm volatile(
        "mma.sync.aligned.m16n8k8.row.col.f32.tf32.tf32.f32 "
        "{%0,%1,%2,%3}, {%4,%5,%6,%7}, {%8,%9}, {%0,%1,%2,%3};\n"
        : "+f"(c[0]), "+f"(c[1]), "+f"(c[2]), "+f"(c[3])
        : "r"(a[0]), "r"(a[1]), "r"(a[2]), "r"(a[3]),
          "r"(b[0]), "r"(b[1]));
}

__device__ __forceinline__ void cp16(uint32_t saddr, const void* g) {
    asm volatile("cp.async.cg.shared.global [%0], [%1], 16;" :: "r"(saddr), "l"(g));
}
#define CP_COMMIT() asm volatile("cp.async.commit_group;" ::: "memory")
#define CP_WAIT1()  asm volatile("cp.async.wait_group 1;" ::: "memory")

// ---------------- router part 1: mean over T ----------------
__global__ void rmean_kernel(const float* __restrict__ x, float* __restrict__ mean) {
    int b = blockIdx.x;
    int d = threadIdx.x;            // 768 threads
    float s = 0.f;
    const float* xb = x + (long)b * Tc * Dc + d;
    #pragma unroll 8
    for (int t = 0; t < Tc; t++) s += xb[(long)t * Dc];
    mean[b * Dc + d] = s * (1.0f / (float)Tc);
}

// ---------------- router part 2: MLP -> argmax experts ----------------
__global__ void router_kernel(const float* __restrict__ mean,
                              const float* __restrict__ w1, const float* __restrict__ b1,
                              const float* __restrict__ w2, const float* __restrict__ b2,
                              int* __restrict__ idx_s, int* __restrict__ idx_t) {
    int b = blockIdx.x;
    int j = threadIdx.x;            // 128 threads
    __shared__ float h[128];
    __shared__ float lg[8];
    float a = b1[j];
    const float* mb = mean + b * Dc;
    const float* wr = w1 + j * Dc;
    for (int d = 0; d < Dc; d++) a += mb[d] * wr[d];
    h[j] = gelu_exact(a);
    __syncthreads();
    if (j < 8) {
        float a2 = b2[j];
        const float* wrr = w2 + j * 128;
        for (int i = 0; i < 128; i++) a2 += h[i] * wrr[i];
        lg[j] = a2;
    }
    __syncthreads();
    if (j == 0) {
        int bi = 0;
        for (int i = 1; i < 4; i++) if (lg[i] > lg[bi]) bi = i;
        idx_s[b] = bi;
        int bt = 4;
        for (int i = 5; i < 8; i++) if (lg[i] > lg[bt]) bt = i;
        idx_t[b] = bt - 4;
    }
}

// ---------------- LayerNorm over D=768, one row per block ----------------
__global__ __launch_bounds__(256)
void ln_kernel(const float* __restrict__ x, const float* __restrict__ g,
               const float* __restrict__ bet, float* __restrict__ o) {
    long row = blockIdx.x;
    int tid = threadIdx.x;
    const float* xr = x + row * Dc;
    float v0 = xr[tid], v1 = xr[tid + 256], v2 = xr[tid + 512];
    float s  = v0 + v1 + v2;
    float ss = v0 * v0 + v1 * v1 + v2 * v2;
    #pragma unroll
    for (int off = 16; off > 0; off >>= 1) {
        s  += __shfl_xor_sync(0xffffffffu, s,  off);
        ss += __shfl_xor_sync(0xffffffffu, ss, off);
    }
    __shared__ float rs[8], rss[8];
    int lane = tid & 31, wid = tid >> 5;
    if (lane == 0) { rs[wid] = s; rss[wid] = ss; }
    __syncthreads();
    if (tid == 0) {
        float S = 0.f, SS = 0.f;
        for (int i = 0; i < 8; i++) { S += rs[i]; SS += rss[i]; }
        float mean = S * (1.0f / (float)Dc);
        float var  = SS * (1.0f / (float)Dc) - mean * mean;
        rs[0] = mean;
        rss[0] = rsqrtf(var + 1e-5f);
    }
    __syncthreads();
    float mean = rs[0], inv = rss[0];
    float* orow = o + row * Dc;
    orow[tid]       = (v0 - mean) * inv * g[tid]       + bet[tid];
    orow[tid + 256] = (v1 - mean) * inv * g[tid + 256] + bet[tid + 256];
    orow[tid + 512] = (v2 - mean) * inv * g[tid + 512] + bet[tid + 512];
}

// ------------- tensor-core GEMM: C = act(A @ W^T + bias) [+ resid] ------------
// TF32 mma.sync m16n8k8, fp32 accumulate, raw-fp32-bit operands (truncation).
// cp.async 3-stage pipeline, tiles 128x128x32, 256 threads = 8 warps (2M x 4N).
// Up to 3 "slices" (independent W/bias/C sets sharing grid) per launch.
struct GArgs {
    const float* A[3];
    const float* W[3];
    const float* bias[3];
    const float* resid[3];
    float* C[3];
    int ldc[3];
    int lda, ldw;
    long wstride;
    int bstride;
    const int* eidx;
    int Kdim, act, tilesN;
};

#define GSTAGE_U32 (2 * 128 * 36)
#define GEMM_SMEM  (3 * GSTAGE_U32 * 4)

__global__ __launch_bounds__(256)
void gemm_tc(GArgs g) {
    extern __shared__ uint32_t sm[];
    const uint32_t sb = (uint32_t)__cvta_generic_to_shared(sm);

    const int tid  = threadIdx.x;
    const int wid  = tid >> 5;
    const int lane = tid & 31;
    const int grp  = lane >> 2;        // 0..7
    const int tg   = lane & 3;         // 0..3
    const int warpM = wid & 1;         // 0..1  (64 rows each)
    const int warpN = wid >> 1;        // 0..3  (32 cols each)

    const int slice = blockIdx.y / g.tilesN;
    const int n0 = (blockIdx.y % g.tilesN) * 128;
    const int bz = blockIdx.z;
    const long rowBase = ((long)bz * gridDim.x + blockIdx.x) * 128;

    const int e = g.eidx ? g.eidx[bz] : 0;
    const float* Ab = g.A[slice] + rowBase * g.lda;
    const float* Wb = g.W[slice] + (long)e * g.wstride + (long)n0 * g.ldw;
    const float* bb = g.bias[slice] + (long)e * g.bstride + n0;
    const float* resid = g.resid[slice];
    float* C = g.C[slice];
    const int ldc = g.ldc[slice];

    float acc[4][4][4];
    #pragma unroll
    for (int i = 0; i < 4; i++)
        #pragma unroll
        for (int j = 0; j < 4; j++)
            #pragma unroll
            for (int r = 0; r < 4; r++) acc[i][j][r] = 0.f;

    // tile load mapping: 128 rows x 32 floats; 2 threads/row, 16 floats each
    const int lrow = tid >> 1;
    const int lcol = (tid & 1) * 16;
    const float* aptr = Ab + (long)lrow * g.lda + lcol;
    const float* wptr = Wb + (long)lrow * g.ldw + lcol;
    const uint32_t soff = (lrow * 36 + lcol) * 4;

    const int nK = g.Kdim >> 5;

    // prologue: stages 0,1
    #pragma unroll
    for (int s = 0; s < 2; s++) {
        uint32_t as = sb + s * (GSTAGE_U32 * 4) + soff;
        uint32_t bs = as + 128 * 36 * 4;
        const float* ap = aptr + s * 32;
        const float* wp = wptr + s * 32;
        #pragma unroll
        for (int q = 0; q < 4; q++) {
            cp16(as + q * 16, ap + q * 4);
            cp16(bs + q * 16, wp + q * 4);
        }
        CP_COMMIT();
    }

    for (int kt = 0; kt < nK; kt++) {
        CP_WAIT1();
        __syncthreads();

        const int nt = kt + 2;
        if (nt < nK) {
            const int s = nt % 3;
            uint32_t as = sb + s * (GSTAGE_U32 * 4) + soff;
            uint32_t bs = as + 128 * 36 * 4;
            const float* ap = aptr + nt * 32;
            const float* wp = wptr + nt * 32;
            #pragma unroll
            for (int q = 0; q < 4; q++) {
                cp16(as + q * 16, ap + q * 4);
                cp16(bs + q * 16, wp + q * 4);
            }
        }
        CP_COMMIT();

        const uint32_t* Asb = sm + (kt % 3) * GSTAGE_U32;
        const uint32_t* Bsb = Asb + 128 * 36;

        #pragma unroll
        for (int kk = 0; kk < 4; kk++) {
            const int k = kk * 8 + tg;
            uint32_t afr[4][4];
            #pragma unroll
            for (int i = 0; i < 4; i++) {
                const int m = warpM * 64 + i * 16 + grp;
                afr[i][0] = Asb[m * 36 + k];
                afr[i][1] = Asb[(m + 8) * 36 + k];
                afr[i][2] = Asb[m * 36 + k + 4];
                afr[i][3] = Asb[(m + 8) * 36 + k + 4];
            }
            uint32_t bfr[4][2];
            #pragma unroll
            for (int j = 0; j < 4; j++) {
                const int n = warpN * 32 + j * 8 + grp;
                bfr[j][0] = Bsb[n * 36 + k];
                bfr[j][1] = Bsb[n * 36 + k + 4];
            }
            #pragma unroll
            for (int i = 0; i < 4; i++)
                #pragma unroll
                for (int j = 0; j < 4; j++)
                    mma_tf32(acc[i][j], afr[i], bfr[j]);
        }
    }

    // epilogue
    #pragma unroll
    for (int i = 0; i < 4; i++) {
        const long m0 = rowBase + warpM * 64 + i * 16 + grp;
        #pragma unroll
        for (int j = 0; j < 4; j++) {
            const int coff = warpN * 32 + j * 8 + 2 * tg;
            const int col = n0 + coff;
            #pragma unroll
            for (int rr = 0; rr < 2; rr++) {
                const long row = m0 + rr * 8;
                float v0 = acc[i][j][rr * 2 + 0] + bb[coff];
                float v1 = acc[i][j][rr * 2 + 1] + bb[coff + 1];
                if (g.act == 1) { v0 = gelu_exact(v0); v1 = gelu_exact(v1); }
                if (resid) {
                    const float* rp = resid + row * ldc + col;
                    v0 += rp[0]; v1 += rp[1];
                }
                *(float2*)(C + row * ldc + col) = make_float2(v0, v1);
            }
        }
    }
}

// ---------- tensor-core flash attention: 64 Q-rows/CTA, 64-col KV tiles ----------
// 128 threads = 4 warps; warp w owns Q rows [16w, 16w+16) -> softmax is warp-local.
// TF32 mma (raw fp32 bits) for both S = Q K^T and O += P V. grid = (T/64, H, B).
#define AT_LD  104
#define AT_LDP 72
#define ATT_SMEM ((3*64*AT_LD + 64*AT_LDP) * 4)
__global__ __launch_bounds__(128)
void attn_tc(const float* __restrict__ Qp, int ldq,
             const float* __restrict__ Kp, int ldk,
             const float* __restrict__ Vp, int ldv,
             float* __restrict__ Op, int ldo, int causal) {
    extern __shared__ uint32_t asm_[];
    uint32_t* Qs = asm_;                    // [64][AT_LD]
    uint32_t* Ks = asm_ + 64 * AT_LD;       // [64][AT_LD]
    uint32_t* Vs = asm_ + 2 * 64 * AT_LD;   // [64][AT_LD]
    uint32_t* Ps = asm_ + 3 * 64 * AT_LD;   // [64][AT_LDP]

    const int tid  = threadIdx.x;
    const int lane = tid & 31;
    const int w    = tid >> 5;             // 0..3
    const int grp  = lane >> 2;            // 0..7
    const int tg   = lane & 3;             // 0..3
    const int qt = blockIdx.x;
    const int h  = blockIdx.y;
    const int b  = blockIdx.z;
    const float scale = 0.1020620726159658f;   // 1/sqrt(96)

    const float* Qb = Qp + ((long)b * Tc + qt * 64) * ldq + h * HDc;
    const float* Kb = Kp + (long)b * Tc * ldk + h * HDc;
    const float* Vb = Vp + (long)b * Tc * ldv + h * HDc;

    // load Q tile (64 x 96) raw bits
    for (int i = tid; i < 64 * 24; i += 128) {
        int r = i / 24, c = (i % 24) * 4;
        *(uint4*)&Qs[r * AT_LD + c] = *(const uint4*)(Qb + (long)r * ldq + c);
    }

    float m_lo = -1e30f, m_hi = -1e30f, l_lo = 0.f, l_hi = 0.f;
    float oacc[12][4];
    #pragma unroll
    for (int d = 0; d < 12; d++)
        #pragma unroll
        for (int r = 0; r < 4; r++) oacc[d][r] = 0.f;

    const int m0 = w * 16 + grp;
    const int rowg_lo = qt * 64 + m0;
    const int rowg_hi = rowg_lo + 8;

    const int ktmax = causal ? qt : (Tc / 64 - 1);
    for (int kt = 0; kt <= ktmax; kt++) {
        __syncthreads();
        for (int i = tid; i < 64 * 24; i += 128) {
            int r = i / 24, c = (i % 24) * 4;
            *(uint4*)&Ks[r * AT_LD + c] = *(const uint4*)(Kb + (long)(kt * 64 + r) * ldk + c);
            *(uint4*)&Vs[r * AT_LD + c] = *(const uint4*)(Vb + (long)(kt * 64 + r) * ldv + c);
        }
        __syncthreads();

        // ---- S = Q K^T  (warp tile 16 x 64) ----
        float sacc[8][4];
        #pragma unroll
        for (int j = 0; j < 8; j++)
            #pragma unroll
            for (int r = 0; r < 4; r++) sacc[j][r] = 0.f;

        #pragma unroll
        for (int kk = 0; kk < 12; kk++) {
            const int k = kk * 8 + tg;
            uint32_t a[4];
            a[0] = Qs[m0 * AT_LD + k];
            a[1] = Qs[(m0 + 8) * AT_LD + k];
            a[2] = Qs[m0 * AT_LD + k + 4];
            a[3] = Qs[(m0 + 8) * AT_LD + k + 4];
            #pragma unroll
            for (int j = 0; j < 8; j++) {
                uint32_t bf[2];
                const int n = j * 8 + grp;
                bf[0] = Ks[n * AT_LD + k];
                bf[1] = Ks[n * AT_LD + k + 4];
                mma_tf32(sacc[j], a, bf);
            }
        }

        // ---- scale + causal mask + online softmax (warp-local) ----
        const bool dmask = causal && (kt == qt);
        float mt_lo = -1e30f, mt_hi = -1e30f;
        #pragma unroll
        for (int j = 0; j < 8; j++) {
            const int c = kt * 64 + j * 8 + 2 * tg;
            float s0 = sacc[j][0] * scale;
            float s1 = sacc[j][1] * scale;
            float s2 = sacc[j][2] * scale;
            float s3 = sacc[j][3] * scale;
            if (dmask) {
                if (c     > rowg_lo) s0 = -1e30f;
                if (c + 1 > rowg_lo) s1 = -1e30f;
                if (c     > rowg_hi) s2 = -1e30f;
                if (c + 1 > rowg_hi) s3 = -1e30f;
            }
            sacc[j][0] = s0; sacc[j][1] = s1; sacc[j][2] = s2; sacc[j][3] = s3;
            mt_lo = fmaxf(mt_lo, fmaxf(s0, s1));
            mt_hi = fmaxf(mt_hi, fmaxf(s2, s3));
        }
        mt_lo = fmaxf(mt_lo, __shfl_xor_sync(0xffffffffu, mt_lo, 1));
        mt_lo = fmaxf(mt_lo, __shfl_xor_sync(0xffffffffu, mt_lo, 2));
        mt_hi = fmaxf(mt_hi, __shfl_xor_sync(0xffffffffu, mt_hi, 1));
        mt_hi = fmaxf(mt_hi, __shfl_xor_sync(0xffffffffu, mt_hi, 2));

        const float mn_lo = fmaxf(m_lo, mt_lo);
        const float mn_hi = fmaxf(m_hi, mt_hi);
        const float al_lo = __expf(m_lo - mn_lo);
        const float al_hi = __expf(m_hi - mn_hi);

        float ps_lo = 0.f, ps_hi = 0.f;
        #pragma unroll
        for (int j = 0; j < 8; j++) {
            const int c = j * 8 + 2 * tg;
            float p0 = __expf(sacc[j][0] - mn_lo);
            float p1 = __expf(sacc[j][1] - mn_lo);
            float p2 = __expf(sacc[j][2] - mn_hi);
            float p3 = __expf(sacc[j][3] - mn_hi);
            ps_lo += p0 + p1;
            ps_hi += p2 + p3;
            Ps[m0 * AT_LDP + c]           = __float_as_uint(p0);
            Ps[m0 * AT_LDP + c + 1]       = __float_as_uint(p1);
            Ps[(m0 + 8) * AT_LDP + c]     = __float_as_uint(p2);
            Ps[(m0 + 8) * AT_LDP + c + 1] = __float_as_uint(p3);
        }
        ps_lo += __shfl_xor_sync(0xffffffffu, ps_lo, 1);
        ps_lo += __shfl_xor_sync(0xffffffffu, ps_lo, 2);
        ps_hi += __shfl_xor_sync(0xffffffffu, ps_hi, 1);
        ps_hi += __shfl_xor_sync(0xffffffffu, ps_hi, 2);

        l_lo = l_lo * al_lo + ps_lo;  m_lo = mn_lo;
        l_hi = l_hi * al_hi + ps_hi;  m_hi = mn_hi;
        #pragma unroll
        for (int d = 0; d < 12; d++) {
            oacc[d][0] *= al_lo; oacc[d][1] *= al_lo;
            oacc[d][2] *= al_hi; oacc[d][3] *= al_hi;
        }
        __syncwarp();

        // ---- O += P V  (warp tile 16 x 96) ----
        #pragma unroll
        for (int kc = 0; kc < 8; kc++) {
            const int k = kc * 8 + tg;
            uint32_t a[4];
            a[0] = Ps[m0 * AT_LDP + k];
            a[1] = Ps[(m0 + 8) * AT_LDP + k];
            a[2] = Ps[m0 * AT_LDP + k + 4];
            a[3] = Ps[(m0 + 8) * AT_LDP + k + 4];
            #pragma unroll
            for (int d = 0; d < 12; d++) {
                uint32_t bf[2];
                const int n = d * 8 + grp;
                bf[0] = Vs[k * AT_LD + n];
                bf[1] = Vs[(k + 4) * AT_LD + n];
                mma_tf32(oacc[d], a, bf);
            }
        }
    }

    // ---- epilogue: normalize by l, write O ----
    const float inv_lo = 1.0f / l_lo;
    const float inv_hi = 1.0f / l_hi;
    float* Ob = Op + ((long)b * Tc + qt * 64 + w * 16) * ldo + h * HDc;
    #pragma unroll
    for (int d = 0; d < 12; d++) {
        const int c = d * 8 + 2 * tg;
        *(float2*)(Ob + (long)grp * ldo + c) =
            make_float2(oacc[d][0] * inv_lo, oacc[d][1] * inv_lo);
        *(float2*)(Ob + (long)(grp + 8) * ldo + c) =
            make_float2(oacc[d][2] * inv_hi, oacc[d][3] * inv_hi);
    }
}

// ---------------- host driver ----------------
static GArgs mkargs() { GArgs g; for (int i = 0; i < 3; i++) { g.A[i]=0; g.W[i]=0; g.bias[i]=0; g.resid[i]=0; g.C[i]=0; g.ldc[i]=0; } g.eidx=0; g.bstride=0; g.wstride=0; g.act=0; return g; }

extern "C" void kernel_launch(void* const* d_in, const int* in_sizes, int n_in,
                              void* d_out, int out_size) {
    (void)in_sizes; (void)n_in; (void)out_size;
    const float* x       = (const float*)d_in[0];
    const float* r_w1    = (const float*)d_in[1];
    const float* r_b1    = (const float*)d_in[2];
    const float* r_w2    = (const float*)d_in[3];
    const float* r_b2    = (const float*)d_in[4];
    const float* ns_g    = (const float*)d_in[5];
    const float* ns_b    = (const float*)d_in[6];
    const float* nt_g    = (const float*)d_in[7];
    const float* nt_b    = (const float*)d_in[8];
    const float* nm_g    = (const float*)d_in[9];
    const float* nm_b    = (const float*)d_in[10];
    const float* sp_wqkv = (const float*)d_in[11];
    const float* sp_bqkv = (const float*)d_in[12];
    const float* sp_wo   = (const float*)d_in[13];
    const float* sp_bo   = (const float*)d_in[14];
    const float* tp_wq   = (const float*)d_in[15];
    const float* tp_bq   = (const float*)d_in[16];
    const float* tp_wk   = (const float*)d_in[17];
    const float* tp_bk   = (const float*)d_in[18];
    const float* tp_wv   = (const float*)d_in[19];
    const float* tp_bv   = (const float*)d_in[20];
    const float* tp_wo   = (const float*)d_in[21];
    const float* tp_bo   = (const float*)d_in[22];
    const float* c_wqkv  = (const float*)d_in[23];
    const float* c_bqkv  = (const float*)d_in[24];
    const float* c_wo    = (const float*)d_in[25];
    const float* c_bo    = (const float*)d_in[26];
    const float* m_w1    = (const float*)d_in[27];
    const float* m_b1    = (const float*)d_in[28];
    const float* m_w2    = (const float*)d_in[29];
    const float* m_b2    = (const float*)d_in[30];
    float* out = (float*)d_out;

    float *mean, *xns, *xt, *qkv, *qt, *kt, *vt, *att, *spat, *temp, *cq, *ckv, *x1, *xm, *y;
    int *idx_s, *idx_t;
    cudaGetSymbolAddress((void**)&mean,  g_mean);
    cudaGetSymbolAddress((void**)&idx_s, g_idx_s);
    cudaGetSymbolAddress((void**)&idx_t, g_idx_t);
    cudaGetSymbolAddress((void**)&xns,   g_xns);
    cudaGetSymbolAddress((void**)&xt,    g_xt);
    cudaGetSymbolAddress((void**)&qkv,   g_qkv);
    cudaGetSymbolAddress((void**)&qt,    g_qt);
    cudaGetSymbolAddress((void**)&kt,    g_kt);
    cudaGetSymbolAddress((void**)&vt,    g_vt);
    cudaGetSymbolAddress((void**)&att,   g_att);
    cudaGetSymbolAddress((void**)&spat,  g_spat);
    cudaGetSymbolAddress((void**)&temp,  g_temp);
    cudaGetSymbolAddress((void**)&cq,    g_cq);
    cudaGetSymbolAddress((void**)&ckv,   g_ckv);
    cudaGetSymbolAddress((void**)&x1,    g_x1);
    cudaGetSymbolAddress((void**)&xm,    g_xm);
    cudaGetSymbolAddress((void**)&y,     g_y);

    cudaFuncSetAttribute(gemm_tc, cudaFuncAttributeMaxDynamicSharedMemorySize, GEMM_SMEM);
    cudaFuncSetAttribute(attn_tc, cudaFuncAttributeMaxDynamicSharedMemorySize, ATT_SMEM);

    // router
    rmean_kernel<<<Bc, Dc>>>(x, mean);
    router_kernel<<<Bc, 128>>>(mean, r_w1, r_b1, r_w2, r_b2, idx_s, idx_t);

    // layernorms for both branches
    ln_kernel<<<BTc, 256>>>(x, ns_g, ns_b, xns);
    ln_kernel<<<BTc, 256>>>(x, nt_g, nt_b, xt);

    // ---- spatial qkv ----
    {
        GArgs a = mkargs();
        a.A[0] = xns; a.W[0] = sp_wqkv; a.bias[0] = sp_bqkv; a.C[0] = qkv; a.ldc[0] = 3 * Dc;
        a.lda = Dc; a.ldw = Dc; a.wstride = (long)3 * Dc * Dc; a.bstride = 3 * Dc;
        a.eidx = idx_s; a.Kdim = Dc; a.act = 0; a.tilesN = 18;
        gemm_tc<<<dim3(4, 18, 8), 256, GEMM_SMEM>>>(a);
    }
    attn_tc<<<dim3(8, 8, 8), 128, ATT_SMEM>>>(qkv, 3 * Dc, qkv + Dc, 3 * Dc,
                                              qkv + 2 * Dc, 3 * Dc, att, Dc, 0);
    {
        GArgs a = mkargs();
        a.A[0] = att; a.W[0] = sp_wo; a.bias[0] = sp_bo; a.C[0] = spat; a.ldc[0] = Dc;
        a.lda = Dc; a.ldw = Dc; a.wstride = (long)Dc * Dc; a.bstride = Dc;
        a.eidx = idx_s; a.Kdim = Dc; a.act = 0; a.tilesN = 6;
        gemm_tc<<<dim3(4, 6, 8), 256, GEMM_SMEM>>>(a);
    }

    // ---- temporal q/k/v fused into one launch ----
    {
        GArgs a = mkargs();
        a.A[0] = xt; a.W[0] = tp_wq; a.bias[0] = tp_bq; a.C[0] = qt; a.ldc[0] = Dc;
        a.A[1] = xt; a.W[1] = tp_wk; a.bias[1] = tp_bk; a.C[1] = kt; a.ldc[1] = Dc;
        a.A[2] = xt; a.W[2] = tp_wv; a.bias[2] = tp_bv; a.C[2] = vt; a.ldc[2] = Dc;
        a.lda = Dc; a.ldw = Dc; a.wstride = (long)Dc * Dc; a.bstride = Dc;
        a.eidx = idx_t; a.Kdim = Dc; a.act = 0; a.tilesN = 6;
        gemm_tc<<<dim3(4, 18, 8), 256, GEMM_SMEM>>>(a);
    }
    attn_tc<<<dim3(8, 8, 8), 128, ATT_SMEM>>>(qt, Dc, kt, Dc, vt, Dc, att, Dc, 1);
    {
        GArgs a = mkargs();
        a.A[0] = att; a.W[0] = tp_wo; a.bias[0] = tp_bo; a.C[0] = temp; a.ldc[0] = Dc;
        a.resid[0] = xt;
        a.lda = Dc; a.ldw = Dc; a.wstride = (long)Dc * Dc; a.bstride = Dc;
        a.eidx = idx_t; a.Kdim = Dc; a.act = 0; a.tilesN = 6;
        gemm_tc<<<dim3(4, 6, 8), 256, GEMM_SMEM>>>(a);
    }

    // ---- cross attention: cq / ck / cv fused into one launch ----
    {
        GArgs a = mkargs();
        a.A[0] = spat; a.W[0] = c_wqkv;               a.bias[0] = c_bqkv;          a.C[0] = cq;       a.ldc[0] = Dc;
        a.A[1] = temp; a.W[1] = c_wqkv + Dc * Dc;     a.bias[1] = c_bqkv + Dc;     a.C[1] = ckv;      a.ldc[1] = 2 * Dc;
        a.A[2] = temp; a.W[2] = c_wqkv + 2 * Dc * Dc; a.bias[2] = c_bqkv + 2 * Dc; a.C[2] = ckv + Dc; a.ldc[2] = 2 * Dc;
        a.lda = Dc; a.ldw = Dc; a.wstride = 0; a.bstride = 0;
        a.eidx = 0; a.Kdim = Dc; a.act = 0; a.tilesN = 6;
        gemm_tc<<<dim3(32, 18, 1), 256, GEMM_SMEM>>>(a);
    }
    attn_tc<<<dim3(8, 8, 8), 128, ATT_SMEM>>>(cq, Dc, ckv, 2 * Dc,
                                              ckv + Dc, 2 * Dc, att, Dc, 0);
    {
        GArgs a = mkargs();
        a.A[0] = att; a.W[0] = c_wo; a.bias[0] = c_bo; a.C[0] = x1; a.ldc[0] = Dc;
        a.resid[0] = x;
        a.lda = Dc; a.ldw = Dc; a.wstride = 0; a.bstride = 0;
        a.eidx = 0; a.Kdim = Dc; a.act = 0; a.tilesN = 6;
        gemm_tc<<<dim3(32, 6, 1), 256, GEMM_SMEM>>>(a);
    }

    // ---- MLP with residual ----
    ln_kernel<<<BTc, 256>>>(x1, nm_g, nm_b, xm);
    {
        GArgs a = mkargs();
        a.A[0] = xm; a.W[0] = m_w1; a.bias[0] = m_b1; a.C[0] = y; a.ldc[0] = 4 * Dc;
        a.lda = Dc; a.ldw = Dc; a.wstride = 0; a.bstride = 0;
        a.eidx = 0; a.Kdim = Dc; a.act = 1; a.tilesN = 24;
        gemm_tc<<<dim3(32, 24, 1), 256, GEMM_SMEM>>>(a);
    }
    {
        GArgs a = mkargs();
        a.A[0] = y; a.W[0] = m_w2; a.bias[0] = m_b2; a.C[0] = out; a.ldc[0] = Dc;
        a.resid[0] = x1;
        a.lda = 4 * Dc; a.ldw = 4 * Dc; a.wstride = 0; a.bstride = 0;
        a.eidx = 0; a.Kdim = 4 * Dc; a.act = 0; a.tilesN = 6;
        gemm_tc<<<dim3(32, 6, 1), 256, GEMM_SMEM>>>(a);
    }
}